// round 13
// baseline (speedup 1.0000x reference)
#include <cuda_runtime.h>
#include <math.h>

typedef unsigned long long u64;
#define BS 64
#define SEQ 300
#define D 768
#define G 2304
#define TSTEPS 100
#define MTOT (BS*SEQ)
#define NB 288
#define NT 256
#define DQ (D/4)   // 192

__device__ __align__(16) float g_xpe[(size_t)MTOT*D];
__device__ __align__(16) float g_gi [(size_t)MTOT*G];
__device__ __align__(16) float g_enc[(size_t)MTOT*D];
__device__ __align__(16) float g_mem[(size_t)MTOT*D];
__device__ __align__(16) float g_h[BS*D];
__device__ __align__(16) float g_part [16*BS*G];
__device__ __align__(16) float g_part2[12*BS*G];
__device__ __align__(16) float g_qpart[12*BS*D];
__device__ __align__(16) float g_ctxp[2][BS*D];
__device__ __align__(16) float2 g_stat[2*BS];          // (m, S) per half per batch
__device__ __align__(16) float g_decWc[(size_t)G*D];
__device__ __align__(16) float g_decW0[G];
__device__ unsigned g_cnt[16*64];                      // leaf counters, 256B apart
__device__ unsigned g_root;
__device__ unsigned g_bar_gen;

// ---- two-level tree barrier: 16 leaves x 18 arrivals + 16-way root ----
__device__ __forceinline__ void grid_barrier() {
    __syncthreads();
    if (threadIdx.x == 0) {
        __threadfence();
        unsigned gen = *(volatile unsigned*)&g_bar_gen;
        unsigned leaf = (blockIdx.x & 15) << 6;
        if (atomicAdd(&g_cnt[leaf], 1u) == 17u) {          // 288/16 = 18
            if (atomicAdd(&g_root, 1u) == 15u) {
#pragma unroll
                for (int i = 0; i < 16; i++) *(volatile unsigned*)&g_cnt[i << 6] = 0u;
                *(volatile unsigned*)&g_root = 0u;
                __threadfence();
                *(volatile unsigned*)&g_bar_gen = gen + 1u;
            }
        }
        while (*(volatile unsigned*)&g_bar_gen == gen) { __nanosleep(32); }
    }
    __syncthreads();
}

__device__ __forceinline__ float sigx(float x)  { return __fdividef(1.0f, 1.0f + __expf(-x)); }
__device__ __forceinline__ float tanhx(float x) { return 1.0f - __fdividef(2.0f, __expf(2.0f*x) + 1.0f); }

__device__ __forceinline__ float4 ldcg4(const float* p) {
    return __ldcg(reinterpret_cast<const float4*>(p));
}
__device__ __forceinline__ void add4(float4& a, float4 b) {
    a.x += b.x; a.y += b.y; a.z += b.z; a.w += b.w;
}
__device__ __forceinline__ u64 dup2(float a) {
    u64 r; asm("mov.b64 %0, {%1, %1};" : "=l"(r) : "f"(a)); return r;
}
__device__ __forceinline__ u64 pack2(float a, float b) {
    u64 r; asm("mov.b64 %0, {%1, %2};" : "=l"(r) : "f"(a), "f"(b)); return r;
}
__device__ __forceinline__ u64 ffma2(u64 a, u64 b, u64 c) {
    u64 d; asm("fma.rn.f32x2 %0, %1, %2, %3;" : "=l"(d) : "l"(a), "l"(b), "l"(c)); return d;
}
__device__ __forceinline__ u64 mul2(u64 a, u64 b) {
    u64 d; asm("mul.rn.f32x2 %0, %1, %2;" : "=l"(d) : "l"(a), "l"(b)); return d;
}
__device__ __forceinline__ float2 unp2(u64 v) {
    float2 f; asm("mov.b64 {%0, %1}, %2;" : "=f"(f.x), "=f"(f.y) : "l"(v)); return f;
}
__device__ __forceinline__ float4 f4of(u64 a, u64 b) {
    float4 v;
    asm("mov.b64 {%0, %1}, %2;" : "=f"(v.x), "=f"(v.y) : "l"(a));
    asm("mov.b64 {%0, %1}, %2;" : "=f"(v.z), "=f"(v.w) : "l"(b));
    return v;
}

// packed rational tanh: x must be pre-clamped to [-7.905, 7.905]
#define TANH2(res, xin) do { \
    u64 _x = (xin); \
    u64 _x2 = mul2(_x, _x); \
    u64 _p = ffma2(_x2, tC0, tC1); \
    _p = ffma2(_x2, _p, tC2); \
    _p = ffma2(_x2, _p, tC3); \
    _p = ffma2(_x2, _p, tC4); \
    _p = ffma2(_x2, _p, tC5); \
    _p = ffma2(_x2, _p, tC6); \
    u64 _q = ffma2(_x2, tQ0, tQ1); \
    _q = ffma2(_x2, _q, tQ2); \
    _q = ffma2(_x2, _q, tQ3); \
    u64 _num = mul2(_x, _p); \
    float2 _qf = unp2(_q); \
    u64 _r = pack2(__uint_as_float(0x7EF477D5u - __float_as_uint(_qf.x)), \
                   __uint_as_float(0x7EF477D5u - __float_as_uint(_qf.y))); \
    u64 _nq = _q ^ 0x8000000080000000ULL; \
    _r = mul2(_r, ffma2(_nq, _r, tTWO)); \
    _r = mul2(_r, ffma2(_nq, _r, tTWO)); \
    _r = mul2(_r, ffma2(_nq, _r, tTWO)); \
    (res) = mul2(_num, _r); \
} while (0)

__device__ __forceinline__ float clampt(float x) {
    return fminf(fmaxf(x, -7.90531110763549805f), 7.90531110763549805f);
}

// reductions for 256 threads
__device__ __forceinline__ float redSum(float v, float* red) {
    __syncthreads();
    int lane = threadIdx.x & 31, w = threadIdx.x >> 5;
#pragma unroll
    for (int o = 16; o; o >>= 1) v += __shfl_down_sync(0xffffffffu, v, o);
    if (lane == 0) red[w] = v;
    __syncthreads();
    if (w == 0) {
        float r = (lane < 8) ? red[lane] : 0.0f;
#pragma unroll
        for (int o = 4; o; o >>= 1) r += __shfl_down_sync(0xffffffffu, r, o);
        if (lane == 0) red[0] = r;
    }
    __syncthreads();
    return red[0];
}
__device__ __forceinline__ float redMax(float v, float* red) {
    __syncthreads();
    int lane = threadIdx.x & 31, w = threadIdx.x >> 5;
#pragma unroll
    for (int o = 16; o; o >>= 1) v = fmaxf(v, __shfl_down_sync(0xffffffffu, v, o));
    if (lane == 0) red[w] = v;
    __syncthreads();
    if (w == 0) {
        float r = (lane < 8) ? red[lane] : -1e30f;
#pragma unroll
        for (int o = 4; o; o >>= 1) r = fmaxf(r, __shfl_down_sync(0xffffffffu, r, o));
        if (lane == 0) red[0] = r;
    }
    __syncthreads();
    return red[0];
}

#define FF8(i, aval) do { u64 ad_ = dup2(aval); \
    acc[i][0] = ffma2(ad_, b01.x, acc[i][0]); \
    acc[i][1] = ffma2(ad_, b01.y, acc[i][1]); \
    acc[i][2] = ffma2(ad_, b23.x, acc[i][2]); \
    acc[i][3] = ffma2(ad_, b23.y, acc[i][3]); } while (0)

// ---- small-M GEMM, 256 threads, 64x128 tile, LDS-balanced 8x8 f32x2 microtile ----
// Cp[64, n0..n0+127] = comb(A,A2)[64, kbeg..kbeg+kc) @ B^T ; kc % 8 == 0
// If stat != 0: comb = alpha0(row)*A + alpha1(row)*A2 (softmax half-merge rescale).
// Else if A2 != 0: comb = A + A2. Else comb = A.
__device__ void gemm64b(const float* __restrict__ A, const float* __restrict__ A2,
                        const float* __restrict__ B, float* __restrict__ Cp,
                        int lda, int ldb, int ldc, int n0, int kbeg, int kc,
                        float* __restrict__ As, float* __restrict__ Bs,
                        const float2* __restrict__ stat)
{
    const int tid = threadIdx.x;
    const int ty = tid >> 4, tx = tid & 15;      // compute grid (tid<128): 8 x 16
    const int am = tid & 63, ak4 = tid >> 6;     // A loader (tid<128)
    const int bn = tid & 127, bk4 = tid >> 7;    // B loader (all 256)
    const bool ald = tid < 128;
    float a0s = 1.0f, a1s = 1.0f;
    if (ald && stat) {
        float2 s0 = stat[am];         // (m0, S0) for batch=am
        float2 s1 = stat[BS + am];    // (m1, S1)
        float M = fmaxf(s0.x, s1.x);
        float e0 = __expf(s0.x - M), e1 = __expf(s1.x - M);
        float den = __fdividef(1.0f, s0.y * e0 + s1.y * e1);
        a0s = e0 * den; a1s = e1 * den;
    }
    u64 acc[8][4];
#pragma unroll
    for (int i = 0; i < 8; i++)
#pragma unroll
        for (int j = 0; j < 4; j++) acc[i][j] = 0ull;
    const float* Ap  = A + (size_t)am * lda + kbeg + ak4 * 4;
    const float* A2p = A2 ? A2 + (size_t)am * lda + kbeg + ak4 * 4 : (const float*)0;
    const float* Bp  = B + (size_t)(n0 + bn) * ldb + kbeg + bk4 * 4;
    const int nst = kc >> 3;
    float4 va, vb;
    if (ald) {
        va = ldcg4(Ap);
        if (A2p) {
            float4 y = ldcg4(A2p);
            va.x = a0s*va.x + a1s*y.x; va.y = a0s*va.y + a1s*y.y;
            va.z = a0s*va.z + a1s*y.z; va.w = a0s*va.w + a1s*y.w;
        }
    }
    vb = *(const float4*)Bp;
    if (ald) {
        As[(ak4*4+0)*68+am]=va.x; As[(ak4*4+1)*68+am]=va.y;
        As[(ak4*4+2)*68+am]=va.z; As[(ak4*4+3)*68+am]=va.w;
    }
    Bs[(bk4*4+0)*132+bn]=vb.x; Bs[(bk4*4+1)*132+bn]=vb.y;
    Bs[(bk4*4+2)*132+bn]=vb.z; Bs[(bk4*4+3)*132+bn]=vb.w;
    __syncthreads();
    for (int st = 0; st < nst; st++) {
        if (st + 1 < nst) {
            if (ald) {
                va = ldcg4(Ap + (st+1)*8);
                if (A2p) {
                    float4 y = ldcg4(A2p + (st+1)*8);
                    va.x = a0s*va.x + a1s*y.x; va.y = a0s*va.y + a1s*y.y;
                    va.z = a0s*va.z + a1s*y.z; va.w = a0s*va.w + a1s*y.w;
                }
            }
            vb = *(const float4*)(Bp + (st+1)*8);
        }
        if (ald) {
            const float* Asl = As + (st & 1) * 544;
            const float* Bsl = Bs + (st & 1) * 1056;
#pragma unroll
            for (int kk = 0; kk < 8; kk++) {
                float4 a0 = *(const float4*)(Asl + kk*68 + ty*4);
                float4 a1 = *(const float4*)(Asl + kk*68 + 32 + ty*4);
                ulonglong2 b01 = *(const ulonglong2*)(Bsl + kk*132 + tx*4);
                ulonglong2 b23 = *(const ulonglong2*)(Bsl + kk*132 + 64 + tx*4);
                FF8(0, a0.x); FF8(1, a0.y); FF8(2, a0.z); FF8(3, a0.w);
                FF8(4, a1.x); FF8(5, a1.y); FF8(6, a1.z); FF8(7, a1.w);
            }
        }
        if (st + 1 < nst) {
            float* An = As + ((st+1) & 1) * 544;
            float* Bn = Bs + ((st+1) & 1) * 1056;
            __syncthreads();
            if (ald) {
                An[(ak4*4+0)*68+am]=va.x; An[(ak4*4+1)*68+am]=va.y;
                An[(ak4*4+2)*68+am]=va.z; An[(ak4*4+3)*68+am]=va.w;
            }
            Bn[(bk4*4+0)*132+bn]=vb.x; Bn[(bk4*4+1)*132+bn]=vb.y;
            Bn[(bk4*4+2)*132+bn]=vb.z; Bn[(bk4*4+3)*132+bn]=vb.w;
            __syncthreads();
        }
    }
    if (ald) {
#pragma unroll
        for (int i = 0; i < 8; i++) {
            int r = (i < 4) ? (ty*4 + i) : (32 + ty*4 + (i - 4));
            float* cr = Cp + (size_t)r * ldc + n0;
            *(float4*)(cr + tx*4)      = f4of(acc[i][0], acc[i][1]);
            *(float4*)(cr + 64 + tx*4) = f4of(acc[i][2], acc[i][3]);
        }
    }
}

// ---- big GEMM (f32x2, 128x128 tile, 256 thr): C = A @ B^T + bias ----
__device__ __forceinline__ void sgemm_f2_body(const float* __restrict__ A,
                                              const float* __restrict__ B,
                                              const float* __restrict__ bias,
                                              float* __restrict__ C, int N, int K)
{
    __shared__ __align__(16) float As[2112];
    __shared__ __align__(16) float Bs[2112];
    const int tid = threadIdx.x, ty = tid >> 4, tx = tid & 15;
    const int m0 = blockIdx.y << 7, n0 = blockIdx.x << 7;
    const int lm = tid & 127, lkq = tid >> 7;
    u64 acc[8][4];
#pragma unroll
    for (int i = 0; i < 8; i++)
#pragma unroll
        for (int j = 0; j < 4; j++) acc[i][j] = 0ull;
    const float* Ap = A + (size_t)(m0 + lm) * K + lkq * 4;
    const float* Bp = B + (size_t)(n0 + lm) * K + lkq * 4;
    const int nst = K >> 3;
    float4 va = *(const float4*)Ap, vb = *(const float4*)Bp;
    As[(lkq*4+0)*132+lm]=va.x; As[(lkq*4+1)*132+lm]=va.y;
    As[(lkq*4+2)*132+lm]=va.z; As[(lkq*4+3)*132+lm]=va.w;
    Bs[(lkq*4+0)*132+lm]=vb.x; Bs[(lkq*4+1)*132+lm]=vb.y;
    Bs[(lkq*4+2)*132+lm]=vb.z; Bs[(lkq*4+3)*132+lm]=vb.w;
    __syncthreads();
    for (int st = 0; st < nst; st++) {
        if (st + 1 < nst) {
            va = *(const float4*)(Ap + (st+1)*8);
            vb = *(const float4*)(Bp + (st+1)*8);
        }
        const float* Asl = As + (st & 1) * 1056;
        const float* Bsl = Bs + (st & 1) * 1056;
#pragma unroll
        for (int kk = 0; kk < 8; kk++) {
            float4 a0 = *(const float4*)(Asl + kk*132 + ty*4);
            float4 a1 = *(const float4*)(Asl + kk*132 + 64 + ty*4);
            ulonglong2 b01 = *(const ulonglong2*)(Bsl + kk*132 + tx*4);
            ulonglong2 b23 = *(const ulonglong2*)(Bsl + kk*132 + 64 + tx*4);
            FF8(0, a0.x); FF8(1, a0.y); FF8(2, a0.z); FF8(3, a0.w);
            FF8(4, a1.x); FF8(5, a1.y); FF8(6, a1.z); FF8(7, a1.w);
        }
        if (st + 1 < nst) {
            float* An = As + ((st+1) & 1) * 1056;
            float* Bn = Bs + ((st+1) & 1) * 1056;
            An[(lkq*4+0)*132+lm]=va.x; An[(lkq*4+1)*132+lm]=va.y;
            An[(lkq*4+2)*132+lm]=va.z; An[(lkq*4+3)*132+lm]=va.w;
            Bn[(lkq*4+0)*132+lm]=vb.x; Bn[(lkq*4+1)*132+lm]=vb.y;
            Bn[(lkq*4+2)*132+lm]=vb.z; Bn[(lkq*4+3)*132+lm]=vb.w;
            __syncthreads();
        }
    }
    const int c0 = n0 + tx*4, c1 = n0 + 64 + tx*4;
    float4 bi0 = *(const float4*)(bias + c0);
    float4 bi1 = *(const float4*)(bias + c1);
#pragma unroll
    for (int i = 0; i < 8; i++) {
        int r = m0 + ((i < 4) ? (ty*4 + i) : (64 + ty*4 + i - 4));
        float4 v0 = f4of(acc[i][0], acc[i][1]);
        float4 v1 = f4of(acc[i][2], acc[i][3]);
        v0.x += bi0.x; v0.y += bi0.y; v0.z += bi0.z; v0.w += bi0.w;
        v1.x += bi1.x; v1.y += bi1.y; v1.z += bi1.z; v1.w += bi1.w;
        *(float4*)(C + (size_t)r * N + c0) = v0;
        *(float4*)(C + (size_t)r * N + c1) = v1;
    }
}

__global__ __launch_bounds__(256, 2) void sgemm_gi_kernel(const float* __restrict__ W,
                                                          const float* __restrict__ bias) {
    sgemm_f2_body(g_xpe, W, bias, g_gi, G, D);
}
__global__ __launch_bounds__(256, 2) void sgemm_mem_kernel(const float* __restrict__ W,
                                                           const float* __restrict__ bias) {
    sgemm_f2_body(g_enc, W, bias, g_mem, D, D);
}

__global__ void prep_kernel(const float* __restrict__ x, const float* __restrict__ dWih) {
    size_t idx = (size_t)blockIdx.x * blockDim.x + threadIdx.x;
    if (idx < (size_t)MTOT * D) {
        int k = (int)(idx % D);
        int s = (int)((idx / D) % SEQ);
        const float c = 9.210340371976184f / (float)D;
        float dv  = expf(-(float)(k & ~1) * c);
        float arg = (float)s * dv;
        g_xpe[idx] = x[idx] + ((k & 1) ? cosf(arg) : sinf(arg));
    }
    if (idx < (size_t)G * D) {
        int g = (int)(idx / D), k = (int)(idx % D);
        g_decWc[idx] = dWih[(size_t)g * (D + 1) + 1 + k];
    }
    if (idx < G) g_decW0[idx] = dWih[(size_t)idx * (D + 1)];
    if (idx < BS * D) g_h[idx] = 0.0f;
}

// ---- persistent encoder: 18 n-tiles(128) x 16 split-K(48) = 288 blocks ----
__global__ __launch_bounds__(NT, 2) void encoder_kernel(const float* __restrict__ Whh,
                                                        const float* __restrict__ bhh)
{
    __shared__ __align__(16) float As[1088];
    __shared__ __align__(16) float Bs[2112];
    const int bx = blockIdx.x, tid = threadIdx.x;
    const int nt = bx >> 4, kz = bx & 15;
    float* Cp = g_part + (size_t)kz * BS * G;
    // gate: 12288 float4 items over 288 blocks (192 x 43 + 96 x 42)
    const int chunk = (bx < 192) ? 43 : 42;
    const int start = bx * 42 + ((bx < 192) ? bx : 192);
    const int gitem = (tid < chunk) ? (start + tid) : -1;
    const int gb = (gitem >= 0) ? (gitem / DQ) : 0;
    const int gj = (gitem >= 0) ? ((gitem - gb * DQ) << 2) : 0;

    for (int s = 0; s < SEQ; s++) {
        gemm64b(g_h, 0, Whh, Cp, D, D, G, nt << 7, kz * 48, 48, As, Bs, 0);
        grid_barrier();
        if (gitem >= 0) {
            float4 t0 = make_float4(0.f,0.f,0.f,0.f), t1 = t0, t2 = t0;
#pragma unroll
            for (int z = 0; z < 16; z++) {
                const float* P = g_part + (size_t)(z * BS + gb) * G + gj;
                add4(t0, ldcg4(P)); add4(t1, ldcg4(P + D)); add4(t2, ldcg4(P + 2*D));
            }
            const float* gip = g_gi + ((size_t)gb * SEQ + s) * G + gj;
            float4 gr = ldcg4(gip), gz = ldcg4(gip + D), gn = ldcg4(gip + 2*D);
            float4 br = *(const float4*)(bhh + gj);
            float4 bz = *(const float4*)(bhh + D + gj);
            float4 bn = *(const float4*)(bhh + 2*D + gj);
            float4 hp = ldcg4(g_h + gb * D + gj);
            float4 hn;
            float r, zt, n;
            r = sigx(gr.x + br.x + t0.x); zt = sigx(gz.x + bz.x + t1.x);
            n = tanhx(gn.x + r * (bn.x + t2.x)); hn.x = (1.f - zt) * n + zt * hp.x;
            r = sigx(gr.y + br.y + t0.y); zt = sigx(gz.y + bz.y + t1.y);
            n = tanhx(gn.y + r * (bn.y + t2.y)); hn.y = (1.f - zt) * n + zt * hp.y;
            r = sigx(gr.z + br.z + t0.z); zt = sigx(gz.z + bz.z + t1.z);
            n = tanhx(gn.z + r * (bn.z + t2.z)); hn.z = (1.f - zt) * n + zt * hp.z;
            r = sigx(gr.w + br.w + t0.w); zt = sigx(gz.w + bz.w + t1.w);
            n = tanhx(gn.w + r * (bn.w + t2.w)); hn.w = (1.f - zt) * n + zt * hp.w;
            *(float4*)(g_h + gb * D + gj) = hn;
            *(float4*)(g_enc + ((size_t)gb * SEQ + s) * D + gj) = hn;
        }
        grid_barrier();
    }
}

// ---- persistent decoder: 288 blocks x 256 threads, 4 phases/step ----
__global__ __launch_bounds__(NT, 2) void decoder_kernel(
    const float* __restrict__ qW,  const float* __restrict__ qb,
    const float* __restrict__ pW,  const float* __restrict__ pb,
    const float* __restrict__ dWih, const float* __restrict__ dWhh,
    const float* __restrict__ bih, const float* __restrict__ bhh,
    const float* __restrict__ tW,  const float* __restrict__ tb,
    float* __restrict__ out)
{
    __shared__ __align__(16) float As[1088];
    __shared__ __align__(16) float Bs[2112];
    __shared__ __align__(16) float s_q[D];
    __shared__ __align__(16) float s_pw[D];
    __shared__ float s_w[160];
    __shared__ float red[8];
    const int bx = blockIdx.x, tid = threadIdx.x;

    {
        int idx = bx * NT + tid;
        if (idx < BS * D) g_h[idx] = 0.0f;   // decoder h0 = zeros
    }
    grid_barrier();

    for (int t = 0; t < TSTEPS; t++) {
        // P1: fused q + gh GEMMs (24 n-tiles(128) x 12 split-K, kc=64)
        {
            int nt = bx / 12, kz = bx % 12;
            const float* Bsel; float* Cp; int n0s, ldcs;
            if (nt < 6) { Bsel = qW;   n0s = nt << 7;       Cp = g_qpart + (size_t)kz * BS * D; ldcs = D; }
            else        { Bsel = dWhh; n0s = (nt - 6) << 7; Cp = g_part2 + (size_t)kz * BS * G; ldcs = G; }
            gemm64b(g_h, 0, Bsel, Cp, D, D, ldcs, n0s, kz * 64, 64, As, Bs, 0);
        }
        grid_barrier();
        // P2: logits + LOCAL softmax + unnormalized half-context (128 blocks)
        if (bx < 128) {
            int b = bx >> 1, half = bx & 1;
            int sb = half * 150;
            if (tid < DQ) {
                int j = tid << 2;
                float4 v = *(const float4*)(qb + j);
#pragma unroll
                for (int z = 0; z < 12; z++)
                    add4(v, ldcg4(g_qpart + (size_t)(z * BS + b) * D + j));
                *(float4*)&s_q[j]  = v;
                *(float4*)&s_pw[j] = *(const float4*)(pW + j);
            }
            __syncthreads();
            const u64 tC0 = dup2(-2.76076847742355e-16f), tC1 = dup2(2.00018790482477e-13f);
            const u64 tC2 = dup2(-8.60467152213735e-11f), tC3 = dup2(5.12229709037114e-08f);
            const u64 tC4 = dup2(1.48572235717979e-05f),  tC5 = dup2(6.37261928875436e-04f);
            const u64 tC6 = dup2(4.89352455891786e-03f);
            const u64 tQ0 = dup2(1.19825839466702e-06f),  tQ1 = dup2(1.18534705686654e-04f);
            const u64 tQ2 = dup2(2.26843463243900e-03f),  tQ3 = dup2(4.89352518554385e-03f);
            const u64 tTWO = dup2(2.0f);
            int w = tid >> 5, lane = tid & 31;
            for (int s = w; s < 150; s += 8) {
                const float* mrow = g_mem + ((size_t)b * SEQ + sb + s) * D;
                u64 acc2 = 0ull;
#pragma unroll
                for (int it = 0; it < 6; it++) {
                    int k = (lane << 2) + it * 128;
                    float4 m4 = ldcg4(mrow + k);
                    float4 q4 = *(const float4*)&s_q[k];
                    u64 xa = pack2(clampt(m4.x + q4.x), clampt(m4.y + q4.y));
                    u64 xb = pack2(clampt(m4.z + q4.z), clampt(m4.w + q4.w));
                    u64 ta, tb2;
                    TANH2(ta, xa);
                    TANH2(tb2, xb);
                    ulonglong2 w2 = *(const ulonglong2*)&s_pw[k];
                    acc2 = ffma2(w2.x, ta, acc2);
                    acc2 = ffma2(w2.y, tb2, acc2);
                }
                float2 af = unp2(acc2);
                float acc = af.x + af.y;
#pragma unroll
                for (int o = 16; o; o >>= 1) acc += __shfl_down_sync(0xffffffffu, acc, o);
                if (lane == 0) s_w[s] = acc;        // pb constant omitted (softmax invariant)
            }
            // local softmax over 150 logits
            float lv = (tid < 150) ? s_w[tid] : -1e30f;
            float m = redMax(lv, red);               // starts with __syncthreads
            float ev = (tid < 150) ? __expf(s_w[tid] - m) : 0.0f;
            float S = redSum(ev, red);
            if (tid < 150) s_w[tid] = ev;
            if (tid == 0) g_stat[half * BS + b] = make_float2(m, S);
            __syncthreads();
            // unnormalized half-context
            if (tid < DQ) {
                float4 c4 = make_float4(0.f, 0.f, 0.f, 0.f);
                const float* ep = g_enc + ((size_t)b * SEQ + sb) * D + (tid << 2);
#pragma unroll 2
                for (int s = 0; s < 150; s++) {
                    float wv = s_w[s];
                    float4 e4 = ldcg4(ep + (size_t)s * D);
                    c4.x += wv * e4.x; c4.y += wv * e4.y;
                    c4.z += wv * e4.z; c4.w += wv * e4.w;
                }
                *(float4*)&g_ctxp[half][b * D + (tid << 2)] = c4;
            }
        }
        grid_barrier();
        // P3: gi = softmax-combined ctx @ decWc^T (18 n-tiles x 16 split-K, kc=48)
        {
            int nt = bx >> 4, kz = bx & 15;
            gemm64b(g_ctxp[0], g_ctxp[1], g_decWc, g_part + (size_t)kz * BS * G,
                    D, D, G, nt << 7, kz * 48, 48, As, Bs, g_stat);
        }
        grid_barrier();
        // P4: gate + prediction (64 blocks)
        if (bx < 64) {
            int b = bx;
            float last = (t == 0) ? 0.0f : __ldcg(&out[b * TSTEPS + t - 1]);
            float psum = 0.0f;
            if (tid < DQ) {
                int j = tid << 2;
                float4 s0 = make_float4(0.f,0.f,0.f,0.f), s1 = s0, s2 = s0;
                float4 u0 = s0, u1 = s0, u2 = s0;
#pragma unroll
                for (int z = 0; z < 16; z++) {
                    const float* P = g_part + (size_t)(z * BS + b) * G + j;
                    add4(s0, ldcg4(P)); add4(s1, ldcg4(P + D)); add4(s2, ldcg4(P + 2*D));
                }
#pragma unroll
                for (int z = 0; z < 12; z++) {
                    const float* Q = g_part2 + (size_t)(z * BS + b) * G + j;
                    add4(u0, ldcg4(Q)); add4(u1, ldcg4(Q + D)); add4(u2, ldcg4(Q + 2*D));
                }
                float4 w0 = *(const float4*)(g_decW0 + j);
                float4 w1 = *(const float4*)(g_decW0 + D + j);
                float4 w2 = *(const float4*)(g_decW0 + 2*D + j);
                float4 b0 = *(const float4*)(bih + j);
                float4 b1 = *(const float4*)(bih + D + j);
                float4 b2 = *(const float4*)(bih + 2*D + j);
                float4 c0 = *(const float4*)(bhh + j);
                float4 c1 = *(const float4*)(bhh + D + j);
                float4 c2 = *(const float4*)(bhh + 2*D + j);
                float4 hp = ldcg4(g_h + b * D + j);
                float4 tw = *(const float4*)(tW + j);
                float4 hn;
                float r, zt, n;
                r  = sigx(b0.x + last * w0.x + s0.x + c0.x + u0.x);
                zt = sigx(b1.x + last * w1.x + s1.x + c1.x + u1.x);
                n  = tanhx(b2.x + last * w2.x + s2.x + r * (c2.x + u2.x));
                hn.x = (1.f - zt) * n + zt * hp.x;
                r  = sigx(b0.y + last * w0.y + s0.y + c0.y + u0.y);
                zt = sigx(b1.y + last * w1.y + s1.y + c1.y + u1.y);
                n  = tanhx(b2.y + last * w2.y + s2.y + r * (c2.y + u2.y));
                hn.y = (1.f - zt) * n + zt * hp.y;
                r  = sigx(b0.z + last * w0.z + s0.z + c0.z + u0.z);
                zt = sigx(b1.z + last * w1.z + s1.z + c1.z + u1.z);
                n  = tanhx(b2.z + last * w2.z + s2.z + r * (c2.z + u2.z));
                hn.z = (1.f - zt) * n + zt * hp.z;
                r  = sigx(b0.w + last * w0.w + s0.w + c0.w + u0.w);
                zt = sigx(b1.w + last * w1.w + s1.w + c1.w + u1.w);
                n  = tanhx(b2.w + last * w2.w + s2.w + r * (c2.w + u2.w));
                hn.w = (1.f - zt) * n + zt * hp.w;
                *(float4*)(g_h + b * D + j) = hn;
                psum = tw.x * hn.x + tw.y * hn.y + tw.z * hn.z + tw.w * hn.w;
            }
            float tot = redSum(psum, red);
            if (tid == 0) out[b * TSTEPS + t] = tot + tb[0];
        }
        grid_barrier();
    }
}

extern "C" void kernel_launch(void* const* d_in, const int* in_sizes, int n_in,
                              void* d_out, int out_size) {
    const float* x       = (const float*)d_in[0];
    const float* enc_Wih = (const float*)d_in[1];
    const float* enc_Whh = (const float*)d_in[2];
    const float* enc_bih = (const float*)d_in[3];
    const float* enc_bhh = (const float*)d_in[4];
    const float* dec_Wih = (const float*)d_in[5];
    const float* dec_Whh = (const float*)d_in[6];
    const float* dec_bih = (const float*)d_in[7];
    const float* dec_bhh = (const float*)d_in[8];
    const float* qW      = (const float*)d_in[9];
    const float* qb      = (const float*)d_in[10];
    const float* mW      = (const float*)d_in[11];
    const float* mb      = (const float*)d_in[12];
    const float* pW      = (const float*)d_in[13];
    const float* pb      = (const float*)d_in[14];
    const float* tW      = (const float*)d_in[15];
    const float* tb      = (const float*)d_in[16];
    float* out = (float*)d_out;

    prep_kernel<<<(MTOT * D + 255) / 256, 256>>>(x, dec_Wih);
    sgemm_gi_kernel<<<dim3(G / 128, MTOT / 128), 256>>>(enc_Wih, enc_bih);
    encoder_kernel<<<NB, NT>>>(enc_Whh, enc_bhh);
    sgemm_mem_kernel<<<dim3(D / 128, MTOT / 128), 256>>>(mW, mb);
    decoder_kernel<<<NB, NT>>>(qW, qb, pW, pb, dec_Wih, dec_Whh,
                               dec_bih, dec_bhh, tW, tb, out);
}

// round 14
// speedup vs baseline: 1.2325x; 1.2325x over previous
#include <cuda_runtime.h>
#include <math.h>

typedef unsigned long long u64;
#define BS 64
#define SEQ 300
#define D 768
#define G 2304
#define TSTEPS 100
#define MTOT (BS*SEQ)
#define NB 288
#define NT 256
#define DQ (D/4)   // 192

__device__ __align__(16) float g_xpe[(size_t)MTOT*D];
__device__ __align__(16) float g_gi [(size_t)MTOT*G];
__device__ __align__(16) float g_enc[(size_t)MTOT*D];
__device__ __align__(16) float g_mem[(size_t)MTOT*D];
__device__ __align__(16) float g_h[BS*D];
__device__ __align__(16) float g_part [16*BS*G];
__device__ __align__(16) float g_part2[12*BS*G];
__device__ __align__(16) float g_qpart[12*BS*D];
__device__ __align__(16) float g_ctxp[4][BS*D];
__device__ __align__(16) float2 g_stat[4*BS];          // (m, S) per quarter per batch
__device__ __align__(16) float g_decWc[(size_t)G*D];
__device__ __align__(16) float g_decW0[G];
__device__ unsigned g_cnt[16*64];
__device__ unsigned g_root;
__device__ unsigned g_bar_gen;

__device__ __forceinline__ void grid_barrier() {
    __syncthreads();
    if (threadIdx.x == 0) {
        __threadfence();
        unsigned gen = *(volatile unsigned*)&g_bar_gen;
        unsigned leaf = (blockIdx.x & 15) << 6;
        if (atomicAdd(&g_cnt[leaf], 1u) == 17u) {
            if (atomicAdd(&g_root, 1u) == 15u) {
#pragma unroll
                for (int i = 0; i < 16; i++) *(volatile unsigned*)&g_cnt[i << 6] = 0u;
                *(volatile unsigned*)&g_root = 0u;
                __threadfence();
                *(volatile unsigned*)&g_bar_gen = gen + 1u;
            }
        }
        while (*(volatile unsigned*)&g_bar_gen == gen) { __nanosleep(32); }
    }
    __syncthreads();
}

__device__ __forceinline__ float sigx(float x)  { return __fdividef(1.0f, 1.0f + __expf(-x)); }
__device__ __forceinline__ float tanhx(float x) { return 1.0f - __fdividef(2.0f, __expf(2.0f*x) + 1.0f); }

__device__ __forceinline__ float4 ldcg4(const float* p) {
    return __ldcg(reinterpret_cast<const float4*>(p));
}
__device__ __forceinline__ void add4(float4& a, float4 b) {
    a.x += b.x; a.y += b.y; a.z += b.z; a.w += b.w;
}
__device__ __forceinline__ u64 dup2(float a) {
    u64 r; asm("mov.b64 %0, {%1, %1};" : "=l"(r) : "f"(a)); return r;
}
__device__ __forceinline__ u64 pack2(float a, float b) {
    u64 r; asm("mov.b64 %0, {%1, %2};" : "=l"(r) : "f"(a), "f"(b)); return r;
}
__device__ __forceinline__ u64 ffma2(u64 a, u64 b, u64 c) {
    u64 d; asm("fma.rn.f32x2 %0, %1, %2, %3;" : "=l"(d) : "l"(a), "l"(b), "l"(c)); return d;
}
__device__ __forceinline__ u64 mul2(u64 a, u64 b) {
    u64 d; asm("mul.rn.f32x2 %0, %1, %2;" : "=l"(d) : "l"(a), "l"(b)); return d;
}
__device__ __forceinline__ float2 unp2(u64 v) {
    float2 f; asm("mov.b64 {%0, %1}, %2;" : "=f"(f.x), "=f"(f.y) : "l"(v)); return f;
}
__device__ __forceinline__ float4 f4of(u64 a, u64 b) {
    float4 v;
    asm("mov.b64 {%0, %1}, %2;" : "=f"(v.x), "=f"(v.y) : "l"(a));
    asm("mov.b64 {%0, %1}, %2;" : "=f"(v.z), "=f"(v.w) : "l"(b));
    return v;
}

#define TANH2(res, xin) do { \
    u64 _x = (xin); \
    u64 _x2 = mul2(_x, _x); \
    u64 _p = ffma2(_x2, tC0, tC1); \
    _p = ffma2(_x2, _p, tC2); \
    _p = ffma2(_x2, _p, tC3); \
    _p = ffma2(_x2, _p, tC4); \
    _p = ffma2(_x2, _p, tC5); \
    _p = ffma2(_x2, _p, tC6); \
    u64 _q = ffma2(_x2, tQ0, tQ1); \
    _q = ffma2(_x2, _q, tQ2); \
    _q = ffma2(_x2, _q, tQ3); \
    u64 _num = mul2(_x, _p); \
    float2 _qf = unp2(_q); \
    u64 _r = pack2(__uint_as_float(0x7EF477D5u - __float_as_uint(_qf.x)), \
                   __uint_as_float(0x7EF477D5u - __float_as_uint(_qf.y))); \
    u64 _nq = _q ^ 0x8000000080000000ULL; \
    _r = mul2(_r, ffma2(_nq, _r, tTWO)); \
    _r = mul2(_r, ffma2(_nq, _r, tTWO)); \
    _r = mul2(_r, ffma2(_nq, _r, tTWO)); \
    (res) = mul2(_num, _r); \
} while (0)

__device__ __forceinline__ float clampt(float x) {
    return fminf(fmaxf(x, -7.90531110763549805f), 7.90531110763549805f);
}

__device__ __forceinline__ float redSum(float v, float* red) {
    __syncthreads();
    int lane = threadIdx.x & 31, w = threadIdx.x >> 5;
#pragma unroll
    for (int o = 16; o; o >>= 1) v += __shfl_down_sync(0xffffffffu, v, o);
    if (lane == 0) red[w] = v;
    __syncthreads();
    if (w == 0) {
        float r = (lane < 8) ? red[lane] : 0.0f;
#pragma unroll
        for (int o = 4; o; o >>= 1) r += __shfl_down_sync(0xffffffffu, r, o);
        if (lane == 0) red[0] = r;
    }
    __syncthreads();
    return red[0];
}
__device__ __forceinline__ float redMax(float v, float* red) {
    __syncthreads();
    int lane = threadIdx.x & 31, w = threadIdx.x >> 5;
#pragma unroll
    for (int o = 16; o; o >>= 1) v = fmaxf(v, __shfl_down_sync(0xffffffffu, v, o));
    if (lane == 0) red[w] = v;
    __syncthreads();
    if (w == 0) {
        float r = (lane < 8) ? red[lane] : -1e30f;
#pragma unroll
        for (int o = 4; o; o >>= 1) r = fmaxf(r, __shfl_down_sync(0xffffffffu, r, o));
        if (lane == 0) red[0] = r;
    }
    __syncthreads();
    return red[0];
}

#define FF8(i, aval) do { u64 ad_ = dup2(aval); \
    acc[i][0] = ffma2(ad_, b01.x, acc[i][0]); \
    acc[i][1] = ffma2(ad_, b01.y, acc[i][1]); \
    acc[i][2] = ffma2(ad_, b23.x, acc[i][2]); \
    acc[i][3] = ffma2(ad_, b23.y, acc[i][3]); } while (0)

// ---- small-M GEMM, 256 threads, 64x128 tile, single-sync double buffer ----
// If stat != 0: A = base of 4 quarters (stride BS*D), combined with softmax alphas.
// Else if A2 != 0: A + A2. Else plain A.
__device__ void gemm64b(const float* __restrict__ A, const float* __restrict__ A2,
                        const float* __restrict__ B, float* __restrict__ Cp,
                        int lda, int ldb, int ldc, int n0, int kbeg, int kc,
                        float* __restrict__ As, float* __restrict__ Bs,
                        const float2* __restrict__ stat)
{
    const int tid = threadIdx.x;
    const int ty = tid >> 4, tx = tid & 15;
    const int am = tid & 63, ak4 = tid >> 6;
    const int bn = tid & 127, bk4 = tid >> 7;
    const bool ald = tid < 128;
    float al0 = 1.f, al1 = 1.f, al2 = 1.f, al3 = 1.f;
    if (ald && stat) {
        float2 s0 = stat[am], s1 = stat[BS + am], s2 = stat[2*BS + am], s3 = stat[3*BS + am];
        float M = fmaxf(fmaxf(s0.x, s1.x), fmaxf(s2.x, s3.x));
        float e0 = __expf(s0.x - M), e1 = __expf(s1.x - M);
        float e2 = __expf(s2.x - M), e3 = __expf(s3.x - M);
        float den = __fdividef(1.0f, s0.y*e0 + s1.y*e1 + s2.y*e2 + s3.y*e3);
        al0 = e0*den; al1 = e1*den; al2 = e2*den; al3 = e3*den;
    }
    u64 acc[8][4];
#pragma unroll
    for (int i = 0; i < 8; i++)
#pragma unroll
        for (int j = 0; j < 4; j++) acc[i][j] = 0ull;
    const float* Ap  = A + (size_t)am * lda + kbeg + ak4 * 4;
    const float* A2p = A2 ? A2 + (size_t)am * lda + kbeg + ak4 * 4 : (const float*)0;
    const float* Bp  = B + (size_t)(n0 + bn) * ldb + kbeg + bk4 * 4;
    const int nst = kc >> 3;
    float4 va, vb;
#define LOADA(off) do { \
    if (stat) { \
        float4 q0 = ldcg4(Ap + (off)); \
        float4 q1 = ldcg4(Ap + BS*D + (off)); \
        float4 q2 = ldcg4(Ap + 2*BS*D + (off)); \
        float4 q3 = ldcg4(Ap + 3*BS*D + (off)); \
        va.x = al0*q0.x + al1*q1.x + al2*q2.x + al3*q3.x; \
        va.y = al0*q0.y + al1*q1.y + al2*q2.y + al3*q3.y; \
        va.z = al0*q0.z + al1*q1.z + al2*q2.z + al3*q3.z; \
        va.w = al0*q0.w + al1*q1.w + al2*q2.w + al3*q3.w; \
    } else { \
        va = ldcg4(Ap + (off)); \
        if (A2p) add4(va, ldcg4(A2p + (off))); \
    } } while (0)
    if (ald) LOADA(0);
    vb = *(const float4*)Bp;
    if (ald) {
        As[(ak4*4+0)*68+am]=va.x; As[(ak4*4+1)*68+am]=va.y;
        As[(ak4*4+2)*68+am]=va.z; As[(ak4*4+3)*68+am]=va.w;
    }
    Bs[(bk4*4+0)*132+bn]=vb.x; Bs[(bk4*4+1)*132+bn]=vb.y;
    Bs[(bk4*4+2)*132+bn]=vb.z; Bs[(bk4*4+3)*132+bn]=vb.w;
    __syncthreads();
    for (int st = 0; st < nst; st++) {
        if (st + 1 < nst) {
            if (ald) LOADA((st+1)*8);
            vb = *(const float4*)(Bp + (st+1)*8);
        }
        if (ald) {
            const float* Asl = As + (st & 1) * 544;
            const float* Bsl = Bs + (st & 1) * 1056;
#pragma unroll
            for (int kk = 0; kk < 8; kk++) {
                float4 a0 = *(const float4*)(Asl + kk*68 + ty*4);
                float4 a1 = *(const float4*)(Asl + kk*68 + 32 + ty*4);
                ulonglong2 b01 = *(const ulonglong2*)(Bsl + kk*132 + tx*4);
                ulonglong2 b23 = *(const ulonglong2*)(Bsl + kk*132 + 64 + tx*4);
                FF8(0, a0.x); FF8(1, a0.y); FF8(2, a0.z); FF8(3, a0.w);
                FF8(4, a1.x); FF8(5, a1.y); FF8(6, a1.z); FF8(7, a1.w);
            }
        }
        if (st + 1 < nst) {
            // single sync: double-buffered, prior reader of (st+1)&1 finished 2 syncs ago
            float* An = As + ((st+1) & 1) * 544;
            float* Bn = Bs + ((st+1) & 1) * 1056;
            if (ald) {
                An[(ak4*4+0)*68+am]=va.x; An[(ak4*4+1)*68+am]=va.y;
                An[(ak4*4+2)*68+am]=va.z; An[(ak4*4+3)*68+am]=va.w;
            }
            Bn[(bk4*4+0)*132+bn]=vb.x; Bn[(bk4*4+1)*132+bn]=vb.y;
            Bn[(bk4*4+2)*132+bn]=vb.z; Bn[(bk4*4+3)*132+bn]=vb.w;
            __syncthreads();
        }
    }
#undef LOADA
    if (ald) {
#pragma unroll
        for (int i = 0; i < 8; i++) {
            int r = (i < 4) ? (ty*4 + i) : (32 + ty*4 + (i - 4));
            float* cr = Cp + (size_t)r * ldc + n0;
            *(float4*)(cr + tx*4)      = f4of(acc[i][0], acc[i][1]);
            *(float4*)(cr + 64 + tx*4) = f4of(acc[i][2], acc[i][3]);
        }
    }
}

// ---- big GEMM (f32x2, 128x128 tile, 256 thr): C = A @ B^T + bias ----
__device__ __forceinline__ void sgemm_f2_body(const float* __restrict__ A,
                                              const float* __restrict__ B,
                                              const float* __restrict__ bias,
                                              float* __restrict__ C, int N, int K)
{
    __shared__ __align__(16) float As[2112];
    __shared__ __align__(16) float Bs[2112];
    const int tid = threadIdx.x, ty = tid >> 4, tx = tid & 15;
    const int m0 = blockIdx.y << 7, n0 = blockIdx.x << 7;
    const int lm = tid & 127, lkq = tid >> 7;
    u64 acc[8][4];
#pragma unroll
    for (int i = 0; i < 8; i++)
#pragma unroll
        for (int j = 0; j < 4; j++) acc[i][j] = 0ull;
    const float* Ap = A + (size_t)(m0 + lm) * K + lkq * 4;
    const float* Bp = B + (size_t)(n0 + lm) * K + lkq * 4;
    const int nst = K >> 3;
    float4 va = *(const float4*)Ap, vb = *(const float4*)Bp;
    As[(lkq*4+0)*132+lm]=va.x; As[(lkq*4+1)*132+lm]=va.y;
    As[(lkq*4+2)*132+lm]=va.z; As[(lkq*4+3)*132+lm]=va.w;
    Bs[(lkq*4+0)*132+lm]=vb.x; Bs[(lkq*4+1)*132+lm]=vb.y;
    Bs[(lkq*4+2)*132+lm]=vb.z; Bs[(lkq*4+3)*132+lm]=vb.w;
    __syncthreads();
    for (int st = 0; st < nst; st++) {
        if (st + 1 < nst) {
            va = *(const float4*)(Ap + (st+1)*8);
            vb = *(const float4*)(Bp + (st+1)*8);
        }
        const float* Asl = As + (st & 1) * 1056;
        const float* Bsl = Bs + (st & 1) * 1056;
#pragma unroll
        for (int kk = 0; kk < 8; kk++) {
            float4 a0 = *(const float4*)(Asl + kk*132 + ty*4);
            float4 a1 = *(const float4*)(Asl + kk*132 + 64 + ty*4);
            ulonglong2 b01 = *(const ulonglong2*)(Bsl + kk*132 + tx*4);
            ulonglong2 b23 = *(const ulonglong2*)(Bsl + kk*132 + 64 + tx*4);
            FF8(0, a0.x); FF8(1, a0.y); FF8(2, a0.z); FF8(3, a0.w);
            FF8(4, a1.x); FF8(5, a1.y); FF8(6, a1.z); FF8(7, a1.w);
        }
        if (st + 1 < nst) {
            float* An = As + ((st+1) & 1) * 1056;
            float* Bn = Bs + ((st+1) & 1) * 1056;
            An[(lkq*4+0)*132+lm]=va.x; An[(lkq*4+1)*132+lm]=va.y;
            An[(lkq*4+2)*132+lm]=va.z; An[(lkq*4+3)*132+lm]=va.w;
            Bn[(lkq*4+0)*132+lm]=vb.x; Bn[(lkq*4+1)*132+lm]=vb.y;
            Bn[(lkq*4+2)*132+lm]=vb.z; Bn[(lkq*4+3)*132+lm]=vb.w;
            __syncthreads();
        }
    }
    const int c0 = n0 + tx*4, c1 = n0 + 64 + tx*4;
    float4 bi0 = *(const float4*)(bias + c0);
    float4 bi1 = *(const float4*)(bias + c1);
#pragma unroll
    for (int i = 0; i < 8; i++) {
        int r = m0 + ((i < 4) ? (ty*4 + i) : (64 + ty*4 + i - 4));
        float4 v0 = f4of(acc[i][0], acc[i][1]);
        float4 v1 = f4of(acc[i][2], acc[i][3]);
        v0.x += bi0.x; v0.y += bi0.y; v0.z += bi0.z; v0.w += bi0.w;
        v1.x += bi1.x; v1.y += bi1.y; v1.z += bi1.z; v1.w += bi1.w;
        *(float4*)(C + (size_t)r * N + c0) = v0;
        *(float4*)(C + (size_t)r * N + c1) = v1;
    }
}

__global__ __launch_bounds__(256, 2) void sgemm_gi_kernel(const float* __restrict__ W,
                                                          const float* __restrict__ bias) {
    sgemm_f2_body(g_xpe, W, bias, g_gi, G, D);
}
__global__ __launch_bounds__(256, 2) void sgemm_mem_kernel(const float* __restrict__ W,
                                                           const float* __restrict__ bias) {
    sgemm_f2_body(g_enc, W, bias, g_mem, D, D);
}

__global__ void prep_kernel(const float* __restrict__ x, const float* __restrict__ dWih) {
    size_t idx = (size_t)blockIdx.x * blockDim.x + threadIdx.x;
    if (idx < (size_t)MTOT * D) {
        int k = (int)(idx % D);
        int s = (int)((idx / D) % SEQ);
        const float c = 9.210340371976184f / (float)D;
        float dv  = expf(-(float)(k & ~1) * c);
        float arg = (float)s * dv;
        g_xpe[idx] = x[idx] + ((k & 1) ? cosf(arg) : sinf(arg));
    }
    if (idx < (size_t)G * D) {
        int g = (int)(idx / D), k = (int)(idx % D);
        g_decWc[idx] = dWih[(size_t)g * (D + 1) + 1 + k];
    }
    if (idx < G) g_decW0[idx] = dWih[(size_t)idx * (D + 1)];
    if (idx < BS * D) g_h[idx] = 0.0f;
}

// ---- persistent encoder: 18 n-tiles(128) x 16 split-K(48) = 288 blocks ----
__global__ __launch_bounds__(NT, 2) void encoder_kernel(const float* __restrict__ Whh,
                                                        const float* __restrict__ bhh)
{
    __shared__ __align__(16) float As[1088];
    __shared__ __align__(16) float Bs[2112];
    const int bx = blockIdx.x, tid = threadIdx.x;
    const int nt = bx >> 4, kz = bx & 15;
    float* Cp = g_part + (size_t)kz * BS * G;
    const int chunk = (bx < 192) ? 43 : 42;
    const int start = bx * 42 + ((bx < 192) ? bx : 192);
    const int gitem = (tid < chunk) ? (start + tid) : -1;
    const int gb = (gitem >= 0) ? (gitem / DQ) : 0;
    const int gj = (gitem >= 0) ? ((gitem - gb * DQ) << 2) : 0;

    for (int s = 0; s < SEQ; s++) {
        gemm64b(g_h, 0, Whh, Cp, D, D, G, nt << 7, kz * 48, 48, As, Bs, 0);
        grid_barrier();
        if (gitem >= 0) {
            float4 t0 = make_float4(0.f,0.f,0.f,0.f), t1 = t0, t2 = t0;
#pragma unroll
            for (int z = 0; z < 16; z++) {
                const float* P = g_part + (size_t)(z * BS + gb) * G + gj;
                add4(t0, ldcg4(P)); add4(t1, ldcg4(P + D)); add4(t2, ldcg4(P + 2*D));
            }
            const float* gip = g_gi + ((size_t)gb * SEQ + s) * G + gj;
            float4 gr = ldcg4(gip), gz = ldcg4(gip + D), gn = ldcg4(gip + 2*D);
            float4 br = *(const float4*)(bhh + gj);
            float4 bz = *(const float4*)(bhh + D + gj);
            float4 bn = *(const float4*)(bhh + 2*D + gj);
            float4 hp = ldcg4(g_h + gb * D + gj);
            float4 hn;
            float r, zt, n;
            r = sigx(gr.x + br.x + t0.x); zt = sigx(gz.x + bz.x + t1.x);
            n = tanhx(gn.x + r * (bn.x + t2.x)); hn.x = (1.f - zt) * n + zt * hp.x;
            r = sigx(gr.y + br.y + t0.y); zt = sigx(gz.y + bz.y + t1.y);
            n = tanhx(gn.y + r * (bn.y + t2.y)); hn.y = (1.f - zt) * n + zt * hp.y;
            r = sigx(gr.z + br.z + t0.z); zt = sigx(gz.z + bz.z + t1.z);
            n = tanhx(gn.z + r * (bn.z + t2.z)); hn.z = (1.f - zt) * n + zt * hp.z;
            r = sigx(gr.w + br.w + t0.w); zt = sigx(gz.w + bz.w + t1.w);
            n = tanhx(gn.w + r * (bn.w + t2.w)); hn.w = (1.f - zt) * n + zt * hp.w;
            *(float4*)(g_h + gb * D + gj) = hn;
            *(float4*)(g_enc + ((size_t)gb * SEQ + s) * D + gj) = hn;
        }
        grid_barrier();
    }
}

// ---- persistent decoder: 288 blocks x 256 threads, 4 phases/step ----
__global__ __launch_bounds__(NT, 2) void decoder_kernel(
    const float* __restrict__ qW,  const float* __restrict__ qb,
    const float* __restrict__ pW,  const float* __restrict__ pb,
    const float* __restrict__ dWih, const float* __restrict__ dWhh,
    const float* __restrict__ bih, const float* __restrict__ bhh,
    const float* __restrict__ tW,  const float* __restrict__ tb,
    float* __restrict__ out)
{
    __shared__ __align__(16) float As[1088];
    __shared__ __align__(16) float Bs[2112];
    __shared__ __align__(16) float s_q[D];
    __shared__ __align__(16) float s_pw[D];
    __shared__ float s_w[80];
    __shared__ float red[8];
    const int bx = blockIdx.x, tid = threadIdx.x;

    {
        int idx = bx * NT + tid;
        if (idx < BS * D) g_h[idx] = 0.0f;
    }
    grid_barrier();

    for (int t = 0; t < TSTEPS; t++) {
        // P1: fused q + gh GEMMs (24 n-tiles(128) x 12 split-K, kc=64)
        {
            int nt = bx / 12, kz = bx % 12;
            const float* Bsel; float* Cp; int n0s, ldcs;
            if (nt < 6) { Bsel = qW;   n0s = nt << 7;       Cp = g_qpart + (size_t)kz * BS * D; ldcs = D; }
            else        { Bsel = dWhh; n0s = (nt - 6) << 7; Cp = g_part2 + (size_t)kz * BS * G; ldcs = G; }
            gemm64b(g_h, 0, Bsel, Cp, D, D, ldcs, n0s, kz * 64, 64, As, Bs, 0);
        }
        grid_barrier();
        // P2: logits + local softmax + unnormalized quarter-context (256 blocks)
        if (bx < 256) {
            int b = bx >> 2, qtr = bx & 3;
            int sb = qtr * 75;
            if (tid < DQ) {
                int j = tid << 2;
                float4 v = *(const float4*)(qb + j);
#pragma unroll
                for (int z = 0; z < 12; z++)
                    add4(v, ldcg4(g_qpart + (size_t)(z * BS + b) * D + j));
                *(float4*)&s_q[j]  = v;
                *(float4*)&s_pw[j] = *(const float4*)(pW + j);
            }
            __syncthreads();
            const u64 tC0 = dup2(-2.76076847742355e-16f), tC1 = dup2(2.00018790482477e-13f);
            const u64 tC2 = dup2(-8.60467152213735e-11f), tC3 = dup2(5.12229709037114e-08f);
            const u64 tC4 = dup2(1.48572235717979e-05f),  tC5 = dup2(6.37261928875436e-04f);
            const u64 tC6 = dup2(4.89352455891786e-03f);
            const u64 tQ0 = dup2(1.19825839466702e-06f),  tQ1 = dup2(1.18534705686654e-04f);
            const u64 tQ2 = dup2(2.26843463243900e-03f),  tQ3 = dup2(4.89352518554385e-03f);
            const u64 tTWO = dup2(2.0f);
            int w = tid >> 5, lane = tid & 31;
            for (int s = w; s < 75; s += 8) {
                const float* mrow = g_mem + ((size_t)b * SEQ + sb + s) * D;
                u64 acc2 = 0ull;
#pragma unroll
                for (int it = 0; it < 6; it++) {
                    int k = (lane << 2) + it * 128;
                    float4 m4 = ldcg4(mrow + k);
                    float4 q4 = *(const float4*)&s_q[k];
                    u64 xa = pack2(clampt(m4.x + q4.x), clampt(m4.y + q4.y));
                    u64 xb = pack2(clampt(m4.z + q4.z), clampt(m4.w + q4.w));
                    u64 ta, tb2;
                    TANH2(ta, xa);
                    TANH2(tb2, xb);
                    ulonglong2 w2 = *(const ulonglong2*)&s_pw[k];
                    acc2 = ffma2(w2.x, ta, acc2);
                    acc2 = ffma2(w2.y, tb2, acc2);
                }
                float2 af = unp2(acc2);
                float acc = af.x + af.y;
#pragma unroll
                for (int o = 16; o; o >>= 1) acc += __shfl_down_sync(0xffffffffu, acc, o);
                if (lane == 0) s_w[s] = acc;   // pb omitted (softmax invariant)
            }
            float lv = (tid < 75) ? s_w[tid] : -1e30f;
            float m = redMax(lv, red);
            float ev = (tid < 75) ? __expf(s_w[tid] - m) : 0.0f;
            float S = redSum(ev, red);
            if (tid < 75) s_w[tid] = ev;
            if (tid == 0) g_stat[qtr * BS + b] = make_float2(m, S);
            __syncthreads();
            if (tid < DQ) {
                float4 c4 = make_float4(0.f, 0.f, 0.f, 0.f);
                const float* ep = g_enc + ((size_t)b * SEQ + sb) * D + (tid << 2);
#pragma unroll 3
                for (int s = 0; s < 75; s++) {
                    float wv = s_w[s];
                    float4 e4 = ldcg4(ep + (size_t)s * D);
                    c4.x += wv * e4.x; c4.y += wv * e4.y;
                    c4.z += wv * e4.z; c4.w += wv * e4.w;
                }
                *(float4*)&g_ctxp[qtr][b * D + (tid << 2)] = c4;
            }
        }
        grid_barrier();
        // P3: gi = softmax-combined ctx @ decWc^T (18 n-tiles x 16 split-K)
        {
            int nt = bx >> 4, kz = bx & 15;
            gemm64b(g_ctxp[0], 0, g_decWc, g_part + (size_t)kz * BS * G,
                    D, D, G, nt << 7, kz * 48, 48, As, Bs, g_stat);
        }
        grid_barrier();
        // P4: gate + prediction (64 blocks)
        if (bx < 64) {
            int b = bx;
            float last = (t == 0) ? 0.0f : __ldcg(&out[b * TSTEPS + t - 1]);
            float psum = 0.0f;
            if (tid < DQ) {
                int j = tid << 2;
                float4 s0 = make_float4(0.f,0.f,0.f,0.f), s1 = s0, s2 = s0;
                float4 u0 = s0, u1 = s0, u2 = s0;
#pragma unroll
                for (int z = 0; z < 16; z++) {
                    const float* P = g_part + (size_t)(z * BS + b) * G + j;
                    add4(s0, ldcg4(P)); add4(s1, ldcg4(P + D)); add4(s2, ldcg4(P + 2*D));
                }
#pragma unroll
                for (int z = 0; z < 12; z++) {
                    const float* Q = g_part2 + (size_t)(z * BS + b) * G + j;
                    add4(u0, ldcg4(Q)); add4(u1, ldcg4(Q + D)); add4(u2, ldcg4(Q + 2*D));
                }
                float4 w0 = *(const float4*)(g_decW0 + j);
                float4 w1 = *(const float4*)(g_decW0 + D + j);
                float4 w2 = *(const float4*)(g_decW0 + 2*D + j);
                float4 b0 = *(const float4*)(bih + j);
                float4 b1 = *(const float4*)(bih + D + j);
                float4 b2 = *(const float4*)(bih + 2*D + j);
                float4 c0 = *(const float4*)(bhh + j);
                float4 c1 = *(const float4*)(bhh + D + j);
                float4 c2 = *(const float4*)(bhh + 2*D + j);
                float4 hp = ldcg4(g_h + b * D + j);
                float4 tw = *(const float4*)(tW + j);
                float4 hn;
                float r, zt, n;
                r  = sigx(b0.x + last * w0.x + s0.x + c0.x + u0.x);
                zt = sigx(b1.x + last * w1.x + s1.x + c1.x + u1.x);
                n  = tanhx(b2.x + last * w2.x + s2.x + r * (c2.x + u2.x));
                hn.x = (1.f - zt) * n + zt * hp.x;
                r  = sigx(b0.y + last * w0.y + s0.y + c0.y + u0.y);
                zt = sigx(b1.y + last * w1.y + s1.y + c1.y + u1.y);
                n  = tanhx(b2.y + last * w2.y + s2.y + r * (c2.y + u2.y));
                hn.y = (1.f - zt) * n + zt * hp.y;
                r  = sigx(b0.z + last * w0.z + s0.z + c0.z + u0.z);
                zt = sigx(b1.z + last * w1.z + s1.z + c1.z + u1.z);
                n  = tanhx(b2.z + last * w2.z + s2.z + r * (c2.z + u2.z));
                hn.z = (1.f - zt) * n + zt * hp.z;
                r  = sigx(b0.w + last * w0.w + s0.w + c0.w + u0.w);
                zt = sigx(b1.w + last * w1.w + s1.w + c1.w + u1.w);
                n  = tanhx(b2.w + last * w2.w + s2.w + r * (c2.w + u2.w));
                hn.w = (1.f - zt) * n + zt * hp.w;
                *(float4*)(g_h + b * D + j) = hn;
                psum = tw.x * hn.x + tw.y * hn.y + tw.z * hn.z + tw.w * hn.w;
            }
            float tot = redSum(psum, red);
            if (tid == 0) out[b * TSTEPS + t] = tot + tb[0];
        }
        grid_barrier();
    }
}

extern "C" void kernel_launch(void* const* d_in, const int* in_sizes, int n_in,
                              void* d_out, int out_size) {
    const float* x       = (const float*)d_in[0];
    const float* enc_Wih = (const float*)d_in[1];
    const float* enc_Whh = (const float*)d_in[2];
    const float* enc_bih = (const float*)d_in[3];
    const float* enc_bhh = (const float*)d_in[4];
    const float* dec_Wih = (const float*)d_in[5];
    const float* dec_Whh = (const float*)d_in[6];
    const float* dec_bih = (const float*)d_in[7];
    const float* dec_bhh = (const float*)d_in[8];
    const float* qW      = (const float*)d_in[9];
    const float* qb      = (const float*)d_in[10];
    const float* mW      = (const float*)d_in[11];
    const float* mb      = (const float*)d_in[12];
    const float* pW      = (const float*)d_in[13];
    const float* pb      = (const float*)d_in[14];
    const float* tW      = (const float*)d_in[15];
    const float* tb      = (const float*)d_in[16];
    float* out = (float*)d_out;

    prep_kernel<<<(MTOT * D + 255) / 256, 256>>>(x, dec_Wih);
    sgemm_gi_kernel<<<dim3(G / 128, MTOT / 128), 256>>>(enc_Wih, enc_bih);
    encoder_kernel<<<NB, NT>>>(enc_Whh, enc_bhh);
    sgemm_mem_kernel<<<dim3(D / 128, MTOT / 128), 256>>>(mW, mb);
    decoder_kernel<<<NB, NT>>>(qW, qb, pW, pb, dec_Wih, dec_Whh,
                               dec_bih, dec_bhh, tW, tb, out);
}

// round 15
// speedup vs baseline: 1.3010x; 1.0555x over previous
#include <cuda_runtime.h>
#include <math.h>

typedef unsigned long long u64;
#define BS 64
#define SEQ 300
#define D 768
#define G 2304
#define TSTEPS 100
#define MTOT (BS*SEQ)
#define NB 288
#define NT 256
#define DQ (D/4)

__device__ __align__(16) float g_xpe[(size_t)MTOT*D];
__device__ __align__(16) float g_gi [(size_t)MTOT*G];
__device__ __align__(16) float g_enc[(size_t)MTOT*D];
__device__ __align__(16) float g_mem[(size_t)MTOT*D];
__device__ __align__(16) float g_h[BS*D];
__device__ __align__(16) float g_part [16*BS*G];
__device__ __align__(16) float g_part2[12*BS*G];
__device__ __align__(16) float g_qpart[12*BS*D];
__device__ __align__(16) float g_ctxp[4][BS*D];
__device__ __align__(16) float2 g_stat[4*BS];
__device__ __align__(16) float g_decWc[(size_t)G*D];
__device__ __align__(16) float g_decW0[G];
__device__ unsigned g_cnt[16*64];
__device__ unsigned g_root;
__device__ unsigned g_bar_gen;

__device__ __forceinline__ void grid_barrier() {
    __syncthreads();
    if (threadIdx.x == 0) {
        __threadfence();
        unsigned gen = *(volatile unsigned*)&g_bar_gen;
        unsigned leaf = (blockIdx.x & 15) << 6;
        if (atomicAdd(&g_cnt[leaf], 1u) == 17u) {
            if (atomicAdd(&g_root, 1u) == 15u) {
#pragma unroll
                for (int i = 0; i < 16; i++) *(volatile unsigned*)&g_cnt[i << 6] = 0u;
                *(volatile unsigned*)&g_root = 0u;
                __threadfence();
                *(volatile unsigned*)&g_bar_gen = gen + 1u;
            }
        }
        while (*(volatile unsigned*)&g_bar_gen == gen) { __nanosleep(32); }
    }
    __syncthreads();
}

__device__ __forceinline__ float sigx(float x)  { return __fdividef(1.0f, 1.0f + __expf(-x)); }
__device__ __forceinline__ float tanhx(float x) { return 1.0f - __fdividef(2.0f, __expf(2.0f*x) + 1.0f); }

__device__ __forceinline__ float4 ldcg4(const float* p) {
    return __ldcg(reinterpret_cast<const float4*>(p));
}
__device__ __forceinline__ void add4(float4& a, float4 b) {
    a.x += b.x; a.y += b.y; a.z += b.z; a.w += b.w;
}
__device__ __forceinline__ u64 dup2(float a) {
    u64 r; asm("mov.b64 %0, {%1, %1};" : "=l"(r) : "f"(a)); return r;
}
__device__ __forceinline__ u64 pack2(float a, float b) {
    u64 r; asm("mov.b64 %0, {%1, %2};" : "=l"(r) : "f"(a), "f"(b)); return r;
}
__device__ __forceinline__ u64 ffma2(u64 a, u64 b, u64 c) {
    u64 d; asm("fma.rn.f32x2 %0, %1, %2, %3;" : "=l"(d) : "l"(a), "l"(b), "l"(c)); return d;
}
__device__ __forceinline__ u64 mul2(u64 a, u64 b) {
    u64 d; asm("mul.rn.f32x2 %0, %1, %2;" : "=l"(d) : "l"(a), "l"(b)); return d;
}
__device__ __forceinline__ float2 unp2(u64 v) {
    float2 f; asm("mov.b64 {%0, %1}, %2;" : "=f"(f.x), "=f"(f.y) : "l"(v)); return f;
}
__device__ __forceinline__ float4 f4of(u64 a, u64 b) {
    float4 v;
    asm("mov.b64 {%0, %1}, %2;" : "=f"(v.x), "=f"(v.y) : "l"(a));
    asm("mov.b64 {%0, %1}, %2;" : "=f"(v.z), "=f"(v.w) : "l"(b));
    return v;
}

#define TANH2(res, xin) do { \
    u64 _x = (xin); \
    u64 _x2 = mul2(_x, _x); \
    u64 _p = ffma2(_x2, tC0, tC1); \
    _p = ffma2(_x2, _p, tC2); \
    _p = ffma2(_x2, _p, tC3); \
    _p = ffma2(_x2, _p, tC4); \
    _p = ffma2(_x2, _p, tC5); \
    _p = ffma2(_x2, _p, tC6); \
    u64 _q = ffma2(_x2, tQ0, tQ1); \
    _q = ffma2(_x2, _q, tQ2); \
    _q = ffma2(_x2, _q, tQ3); \
    u64 _num = mul2(_x, _p); \
    float2 _qf = unp2(_q); \
    u64 _r = pack2(__uint_as_float(0x7EF477D5u - __float_as_uint(_qf.x)), \
                   __uint_as_float(0x7EF477D5u - __float_as_uint(_qf.y))); \
    u64 _nq = _q ^ 0x8000000080000000ULL; \
    _r = mul2(_r, ffma2(_nq, _r, tTWO)); \
    _r = mul2(_r, ffma2(_nq, _r, tTWO)); \
    _r = mul2(_r, ffma2(_nq, _r, tTWO)); \
    (res) = mul2(_num, _r); \
} while (0)

__device__ __forceinline__ float clampt(float x) {
    return fminf(fmaxf(x, -7.90531110763549805f), 7.90531110763549805f);
}

__device__ __forceinline__ float redSum(float v, float* red) {
    __syncthreads();
    int lane = threadIdx.x & 31, w = threadIdx.x >> 5;
#pragma unroll
    for (int o = 16; o; o >>= 1) v += __shfl_down_sync(0xffffffffu, v, o);
    if (lane == 0) red[w] = v;
    __syncthreads();
    if (w == 0) {
        float r = (lane < 8) ? red[lane] : 0.0f;
#pragma unroll
        for (int o = 4; o; o >>= 1) r += __shfl_down_sync(0xffffffffu, r, o);
        if (lane == 0) red[0] = r;
    }
    __syncthreads();
    return red[0];
}
__device__ __forceinline__ float redMax(float v, float* red) {
    __syncthreads();
    int lane = threadIdx.x & 31, w = threadIdx.x >> 5;
#pragma unroll
    for (int o = 16; o; o >>= 1) v = fmaxf(v, __shfl_down_sync(0xffffffffu, v, o));
    if (lane == 0) red[w] = v;
    __syncthreads();
    if (w == 0) {
        float r = (lane < 8) ? red[lane] : -1e30f;
#pragma unroll
        for (int o = 4; o; o >>= 1) r = fmaxf(r, __shfl_down_sync(0xffffffffu, r, o));
        if (lane == 0) red[0] = r;
    }
    __syncthreads();
    return red[0];
}

#define FF8(i, aval) do { u64 ad_ = dup2(aval); \
    acc[i][0] = ffma2(ad_, b01.x, acc[i][0]); \
    acc[i][1] = ffma2(ad_, b01.y, acc[i][1]); \
    acc[i][2] = ffma2(ad_, b23.x, acc[i][2]); \
    acc[i][3] = ffma2(ad_, b23.y, acc[i][3]); } while (0)

// ---- streaming small-M GEMM (decoder P1 only): 64x128 tile, single-sync DB ----
__device__ void gemm64b(const float* __restrict__ A, const float* __restrict__ B,
                        float* __restrict__ Cp, int lda, int ldb, int ldc,
                        int n0, int kbeg, int kc,
                        float* __restrict__ As, float* __restrict__ Bs)
{
    const int tid = threadIdx.x;
    const int ty = tid >> 4, tx = tid & 15;
    const int am = tid & 63, ak4 = tid >> 6;
    const int bn = tid & 127, bk4 = tid >> 7;
    const bool ald = tid < 128;
    u64 acc[8][4];
#pragma unroll
    for (int i = 0; i < 8; i++)
#pragma unroll
        for (int j = 0; j < 4; j++) acc[i][j] = 0ull;
    const float* Ap = A + (size_t)am * lda + kbeg + ak4 * 4;
    const float* Bp = B + (size_t)(n0 + bn) * ldb + kbeg + bk4 * 4;
    const int nst = kc >> 3;
    float4 va, vb;
    if (ald) va = ldcg4(Ap);
    vb = *(const float4*)Bp;
    if (ald) {
        As[(ak4*4+0)*68+am]=va.x; As[(ak4*4+1)*68+am]=va.y;
        As[(ak4*4+2)*68+am]=va.z; As[(ak4*4+3)*68+am]=va.w;
    }
    Bs[(bk4*4+0)*132+bn]=vb.x; Bs[(bk4*4+1)*132+bn]=vb.y;
    Bs[(bk4*4+2)*132+bn]=vb.z; Bs[(bk4*4+3)*132+bn]=vb.w;
    __syncthreads();
    for (int st = 0; st < nst; st++) {
        if (st + 1 < nst) {
            if (ald) va = ldcg4(Ap + (st+1)*8);
            vb = *(const float4*)(Bp + (st+1)*8);
        }
        if (ald) {
            const float* Asl = As + (st & 1) * 544;
            const float* Bsl = Bs + (st & 1) * 1056;
#pragma unroll
            for (int kk = 0; kk < 8; kk++) {
                float4 a0 = *(const float4*)(Asl + kk*68 + ty*4);
                float4 a1 = *(const float4*)(Asl + kk*68 + 32 + ty*4);
                ulonglong2 b01 = *(const ulonglong2*)(Bsl + kk*132 + tx*4);
                ulonglong2 b23 = *(const ulonglong2*)(Bsl + kk*132 + 64 + tx*4);
                FF8(0, a0.x); FF8(1, a0.y); FF8(2, a0.z); FF8(3, a0.w);
                FF8(4, a1.x); FF8(5, a1.y); FF8(6, a1.z); FF8(7, a1.w);
            }
        }
        if (st + 1 < nst) {
            float* An = As + ((st+1) & 1) * 544;
            float* Bn = Bs + ((st+1) & 1) * 1056;
            if (ald) {
                An[(ak4*4+0)*68+am]=va.x; An[(ak4*4+1)*68+am]=va.y;
                An[(ak4*4+2)*68+am]=va.z; An[(ak4*4+3)*68+am]=va.w;
            }
            Bn[(bk4*4+0)*132+bn]=vb.x; Bn[(bk4*4+1)*132+bn]=vb.y;
            Bn[(bk4*4+2)*132+bn]=vb.z; Bn[(bk4*4+3)*132+bn]=vb.w;
            __syncthreads();
        }
    }
    if (ald) {
#pragma unroll
        for (int i = 0; i < 8; i++) {
            int r = (i < 4) ? (ty*4 + i) : (32 + ty*4 + (i - 4));
            float* cr = Cp + (size_t)r * ldc + n0;
            *(float4*)(cr + tx*4)      = f4of(acc[i][0], acc[i][1]);
            *(float4*)(cr + 64 + tx*4) = f4of(acc[i][2], acc[i][3]);
        }
    }
}

// ---- resident-B compute: 48 K-steps from resident Bs[48][132] and As[48][68] ----
__device__ __forceinline__ void gemm48_res(const float* __restrict__ As,
                                           const float* __restrict__ Bs,
                                           float* __restrict__ Cp, int ldc, int n0)
{
    const int tid = threadIdx.x;
    const int ty = tid >> 4, tx = tid & 15;
    if (tid >= 128) return;
    u64 acc[8][4];
#pragma unroll
    for (int i = 0; i < 8; i++)
#pragma unroll
        for (int j = 0; j < 4; j++) acc[i][j] = 0ull;
    for (int k0 = 0; k0 < 48; k0 += 8) {
#pragma unroll
        for (int k2 = 0; k2 < 8; k2++) {
            int kk = k0 + k2;
            float4 a0 = *(const float4*)(As + kk*68 + ty*4);
            float4 a1 = *(const float4*)(As + kk*68 + 32 + ty*4);
            ulonglong2 b01 = *(const ulonglong2*)(Bs + kk*132 + tx*4);
            ulonglong2 b23 = *(const ulonglong2*)(Bs + kk*132 + 64 + tx*4);
            FF8(0, a0.x); FF8(1, a0.y); FF8(2, a0.z); FF8(3, a0.w);
            FF8(4, a1.x); FF8(5, a1.y); FF8(6, a1.z); FF8(7, a1.w);
        }
    }
#pragma unroll
    for (int i = 0; i < 8; i++) {
        int r = (i < 4) ? (ty*4 + i) : (32 + ty*4 + (i - 4));
        float* cr = Cp + (size_t)r * ldc + n0;
        *(float4*)(cr + tx*4)      = f4of(acc[i][0], acc[i][1]);
        *(float4*)(cr + 64 + tx*4) = f4of(acc[i][2], acc[i][3]);
    }
}

// ---- big GEMM (f32x2, 128x128 tile): C = A @ B^T + bias ----
__device__ __forceinline__ void sgemm_f2_body(const float* __restrict__ A,
                                              const float* __restrict__ B,
                                              const float* __restrict__ bias,
                                              float* __restrict__ C, int N, int K)
{
    __shared__ __align__(16) float As[2112];
    __shared__ __align__(16) float Bs[2112];
    const int tid = threadIdx.x, ty = tid >> 4, tx = tid & 15;
    const int m0 = blockIdx.y << 7, n0 = blockIdx.x << 7;
    const int lm = tid & 127, lkq = tid >> 7;
    u64 acc[8][4];
#pragma unroll
    for (int i = 0; i < 8; i++)
#pragma unroll
        for (int j = 0; j < 4; j++) acc[i][j] = 0ull;
    const float* Ap = A + (size_t)(m0 + lm) * K + lkq * 4;
    const float* Bp = B + (size_t)(n0 + lm) * K + lkq * 4;
    const int nst = K >> 3;
    float4 va = *(const float4*)Ap, vb = *(const float4*)Bp;
    As[(lkq*4+0)*132+lm]=va.x; As[(lkq*4+1)*132+lm]=va.y;
    As[(lkq*4+2)*132+lm]=va.z; As[(lkq*4+3)*132+lm]=va.w;
    Bs[(lkq*4+0)*132+lm]=vb.x; Bs[(lkq*4+1)*132+lm]=vb.y;
    Bs[(lkq*4+2)*132+lm]=vb.z; Bs[(lkq*4+3)*132+lm]=vb.w;
    __syncthreads();
    for (int st = 0; st < nst; st++) {
        if (st + 1 < nst) {
            va = *(const float4*)(Ap + (st+1)*8);
            vb = *(const float4*)(Bp + (st+1)*8);
        }
        const float* Asl = As + (st & 1) * 1056;
        const float* Bsl = Bs + (st & 1) * 1056;
#pragma unroll
        for (int kk = 0; kk < 8; kk++) {
            float4 a0 = *(const float4*)(Asl + kk*132 + ty*4);
            float4 a1 = *(const float4*)(Asl + kk*132 + 64 + ty*4);
            ulonglong2 b01 = *(const ulonglong2*)(Bsl + kk*132 + tx*4);
            ulonglong2 b23 = *(const ulonglong2*)(Bsl + kk*132 + 64 + tx*4);
            FF8(0, a0.x); FF8(1, a0.y); FF8(2, a0.z); FF8(3, a0.w);
            FF8(4, a1.x); FF8(5, a1.y); FF8(6, a1.z); FF8(7, a1.w);
        }
        if (st + 1 < nst) {
            float* An = As + ((st+1) & 1) * 1056;
            float* Bn = Bs + ((st+1) & 1) * 1056;
            An[(lkq*4+0)*132+lm]=va.x; An[(lkq*4+1)*132+lm]=va.y;
            An[(lkq*4+2)*132+lm]=va.z; An[(lkq*4+3)*132+lm]=va.w;
            Bn[(lkq*4+0)*132+lm]=vb.x; Bn[(lkq*4+1)*132+lm]=vb.y;
            Bn[(lkq*4+2)*132+lm]=vb.z; Bn[(lkq*4+3)*132+lm]=vb.w;
            __syncthreads();
        }
    }
    const int c0 = n0 + tx*4, c1 = n0 + 64 + tx*4;
    float4 bi0 = *(const float4*)(bias + c0);
    float4 bi1 = *(const float4*)(bias + c1);
#pragma unroll
    for (int i = 0; i < 8; i++) {
        int r = m0 + ((i < 4) ? (ty*4 + i) : (64 + ty*4 + i - 4));
        float4 v0 = f4of(acc[i][0], acc[i][1]);
        float4 v1 = f4of(acc[i][2], acc[i][3]);
        v0.x += bi0.x; v0.y += bi0.y; v0.z += bi0.z; v0.w += bi0.w;
        v1.x += bi1.x; v1.y += bi1.y; v1.z += bi1.z; v1.w += bi1.w;
        *(float4*)(C + (size_t)r * N + c0) = v0;
        *(float4*)(C + (size_t)r * N + c1) = v1;
    }
}

__global__ __launch_bounds__(256, 2) void sgemm_gi_kernel(const float* __restrict__ W,
                                                          const float* __restrict__ bias) {
    sgemm_f2_body(g_xpe, W, bias, g_gi, G, D);
}
__global__ __launch_bounds__(256, 2) void sgemm_mem_kernel(const float* __restrict__ W,
                                                           const float* __restrict__ bias) {
    sgemm_f2_body(g_enc, W, bias, g_mem, D, D);
}

__global__ void prep_kernel(const float* __restrict__ x, const float* __restrict__ dWih) {
    size_t idx = (size_t)blockIdx.x * blockDim.x + threadIdx.x;
    if (idx < (size_t)MTOT * D) {
        int k = (int)(idx % D);
        int s = (int)((idx / D) % SEQ);
        const float c = 9.210340371976184f / (float)D;
        float dv  = expf(-(float)(k & ~1) * c);
        float arg = (float)s * dv;
        g_xpe[idx] = x[idx] + ((k & 1) ? cosf(arg) : sinf(arg));
    }
    if (idx < (size_t)G * D) {
        int g = (int)(idx / D), k = (int)(idx % D);
        g_decWc[idx] = dWih[(size_t)g * (D + 1) + 1 + k];
    }
    if (idx < G) g_decW0[idx] = dWih[(size_t)idx * (D + 1)];
    if (idx < BS * D) g_h[idx] = 0.0f;
}

// ---- persistent encoder: resident Whh slice, 18nt x 16kz = 288 blocks ----
__global__ __launch_bounds__(NT, 2) void encoder_kernel(const float* __restrict__ Whh,
                                                        const float* __restrict__ bhh)
{
    __shared__ __align__(16) float Bs[48*132];   // resident Whh slice
    __shared__ __align__(16) float As[48*68];    // per-step h slice
    const int bx = blockIdx.x, tid = threadIdx.x;
    const int nt = bx >> 4, kz = bx & 15;
    const int n0 = nt << 7, kbeg = kz * 48;
    float* Cp = g_part + (size_t)kz * BS * G;
    // load resident B once: 128 rows x 48 cols
    {
        int bn = tid & 127, kq0 = tid >> 7;
#pragma unroll
        for (int i = 0; i < 6; i++) {
            int kq = kq0 + 2 * i;
            float4 v = ldcg4(Whh + (size_t)(n0 + bn) * D + kbeg + (kq << 2));
            Bs[(kq*4+0)*132+bn]=v.x; Bs[(kq*4+1)*132+bn]=v.y;
            Bs[(kq*4+2)*132+bn]=v.z; Bs[(kq*4+3)*132+bn]=v.w;
        }
    }
    const int am = tid & 63, kq0 = tid >> 6;
    const int chunk = (bx < 192) ? 43 : 42;
    const int start = bx * 42 + ((bx < 192) ? bx : 192);
    const int gitem = (tid < chunk) ? (start + tid) : -1;
    const int gb = (gitem >= 0) ? (gitem / DQ) : 0;
    const int gj = (gitem >= 0) ? ((gitem - gb * DQ) << 2) : 0;
    grid_barrier();   // also covers Bs fill + prep ordering

    for (int s = 0; s < SEQ; s++) {
        // fill A (h slice 64x48), 3 float4/thread
#pragma unroll
        for (int i = 0; i < 3; i++) {
            int kq = kq0 + 4 * i;
            float4 v = ldcg4(g_h + (size_t)am * D + kbeg + (kq << 2));
            As[(kq*4+0)*68+am]=v.x; As[(kq*4+1)*68+am]=v.y;
            As[(kq*4+2)*68+am]=v.z; As[(kq*4+3)*68+am]=v.w;
        }
        __syncthreads();
        gemm48_res(As, Bs, Cp, G, n0);
        grid_barrier();
        if (gitem >= 0) {
            float4 t0 = make_float4(0.f,0.f,0.f,0.f), t1 = t0, t2 = t0;
#pragma unroll
            for (int z = 0; z < 16; z++) {
                const float* P = g_part + (size_t)(z * BS + gb) * G + gj;
                add4(t0, ldcg4(P)); add4(t1, ldcg4(P + D)); add4(t2, ldcg4(P + 2*D));
            }
            const float* gip = g_gi + ((size_t)gb * SEQ + s) * G + gj;
            float4 gr = ldcg4(gip), gz = ldcg4(gip + D), gn = ldcg4(gip + 2*D);
            float4 br = *(const float4*)(bhh + gj);
            float4 bz = *(const float4*)(bhh + D + gj);
            float4 bn = *(const float4*)(bhh + 2*D + gj);
            float4 hp = ldcg4(g_h + gb * D + gj);
            float4 hn;
            float r, zt, n;
            r = sigx(gr.x + br.x + t0.x); zt = sigx(gz.x + bz.x + t1.x);
            n = tanhx(gn.x + r * (bn.x + t2.x)); hn.x = (1.f - zt) * n + zt * hp.x;
            r = sigx(gr.y + br.y + t0.y); zt = sigx(gz.y + bz.y + t1.y);
            n = tanhx(gn.y + r * (bn.y + t2.y)); hn.y = (1.f - zt) * n + zt * hp.y;
            r = sigx(gr.z + br.z + t0.z); zt = sigx(gz.z + bz.z + t1.z);
            n = tanhx(gn.z + r * (bn.z + t2.z)); hn.z = (1.f - zt) * n + zt * hp.z;
            r = sigx(gr.w + br.w + t0.w); zt = sigx(gz.w + bz.w + t1.w);
            n = tanhx(gn.w + r * (bn.w + t2.w)); hn.w = (1.f - zt) * n + zt * hp.w;
            *(float4*)(g_h + gb * D + gj) = hn;
            *(float4*)(g_enc + ((size_t)gb * SEQ + s) * D + gj) = hn;
        }
        grid_barrier();
    }
}

// ---- persistent decoder: resident decWc for P3; streaming P1 ----
__global__ __launch_bounds__(NT, 2) void decoder_kernel(
    const float* __restrict__ qW,  const float* __restrict__ qb,
    const float* __restrict__ pW,  const float* __restrict__ pb,
    const float* __restrict__ dWih, const float* __restrict__ dWhh,
    const float* __restrict__ bih, const float* __restrict__ bhh,
    const float* __restrict__ tW,  const float* __restrict__ tb,
    float* __restrict__ out)
{
    __shared__ __align__(16) float Bs3[48*132];      // resident decWc slice
    __shared__ __align__(16) float Un[3328];         // union: P1 As(1088)+Bs(2112) | P3 As3(3264)
    __shared__ __align__(16) float s_q[D];
    __shared__ __align__(16) float s_pw[D];
    __shared__ float s_w[80];
    __shared__ float red[8];
    const int bx = blockIdx.x, tid = threadIdx.x;
    const int nt3 = bx >> 4, kz3 = bx & 15;
    const int n03 = nt3 << 7, kbeg3 = kz3 * 48;
    // resident decWc slice
    {
        int bn = tid & 127, kq0 = tid >> 7;
#pragma unroll
        for (int i = 0; i < 6; i++) {
            int kq = kq0 + 2 * i;
            float4 v = ldcg4(g_decWc + (size_t)(n03 + bn) * D + kbeg3 + (kq << 2));
            Bs3[(kq*4+0)*132+bn]=v.x; Bs3[(kq*4+1)*132+bn]=v.y;
            Bs3[(kq*4+2)*132+bn]=v.z; Bs3[(kq*4+3)*132+bn]=v.w;
        }
    }
    {
        int idx = bx * NT + tid;
        if (idx < BS * D) g_h[idx] = 0.0f;
    }
    grid_barrier();

    for (int t = 0; t < TSTEPS; t++) {
        // P1: fused q + gh GEMMs (24nt x 12kz, kc=64), streaming
        {
            int nt = bx / 12, kz = bx % 12;
            const float* Bsel; float* Cp; int n0s, ldcs;
            if (nt < 6) { Bsel = qW;   n0s = nt << 7;       Cp = g_qpart + (size_t)kz * BS * D; ldcs = D; }
            else        { Bsel = dWhh; n0s = (nt - 6) << 7; Cp = g_part2 + (size_t)kz * BS * G; ldcs = G; }
            gemm64b(g_h, Bsel, Cp, D, D, ldcs, n0s, kz * 64, 64, Un, Un + 1088);
        }
        grid_barrier();
        // P2: logits + local softmax + unnormalized quarter-context (256 blocks)
        if (bx < 256) {
            int b = bx >> 2, qtr = bx & 3;
            int sb = qtr * 75;
            if (tid < DQ) {
                int j = tid << 2;
                float4 v = *(const float4*)(qb + j);
#pragma unroll
                for (int z = 0; z < 12; z++)
                    add4(v, ldcg4(g_qpart + (size_t)(z * BS + b) * D + j));
                *(float4*)&s_q[j]  = v;
                *(float4*)&s_pw[j] = *(const float4*)(pW + j);
            }
            __syncthreads();
            const u64 tC0 = dup2(-2.76076847742355e-16f), tC1 = dup2(2.00018790482477e-13f);
            const u64 tC2 = dup2(-8.60467152213735e-11f), tC3 = dup2(5.12229709037114e-08f);
            const u64 tC4 = dup2(1.48572235717979e-05f),  tC5 = dup2(6.37261928875436e-04f);
            const u64 tC6 = dup2(4.89352455891786e-03f);
            const u64 tQ0 = dup2(1.19825839466702e-06f),  tQ1 = dup2(1.18534705686654e-04f);
            const u64 tQ2 = dup2(2.26843463243900e-03f),  tQ3 = dup2(4.89352518554385e-03f);
            const u64 tTWO = dup2(2.0f);
            int w = tid >> 5, lane = tid & 31;
            for (int s = w; s < 75; s += 8) {
                const float* mrow = g_mem + ((size_t)b * SEQ + sb + s) * D;
                u64 acc2 = 0ull;
#pragma unroll
                for (int it = 0; it < 6; it++) {
                    int k = (lane << 2) + it * 128;
                    float4 m4 = ldcg4(mrow + k);
                    float4 q4 = *(const float4*)&s_q[k];
                    u64 xa = pack2(clampt(m4.x + q4.x), clampt(m4.y + q4.y));
                    u64 xb = pack2(clampt(m4.z + q4.z), clampt(m4.w + q4.w));
                    u64 ta, tb2;
                    TANH2(ta, xa);
                    TANH2(tb2, xb);
                    ulonglong2 w2 = *(const ulonglong2*)&s_pw[k];
                    acc2 = ffma2(w2.x, ta, acc2);
                    acc2 = ffma2(w2.y, tb2, acc2);
                }
                float2 af = unp2(acc2);
                float acc = af.x + af.y;
#pragma unroll
                for (int o = 16; o; o >>= 1) acc += __shfl_down_sync(0xffffffffu, acc, o);
                if (lane == 0) s_w[s] = acc;
            }
            float lv = (tid < 75) ? s_w[tid] : -1e30f;
            float m = redMax(lv, red);
            float ev = (tid < 75) ? __expf(s_w[tid] - m) : 0.0f;
            float S = redSum(ev, red);
            if (tid < 75) s_w[tid] = ev;
            if (tid == 0) g_stat[qtr * BS + b] = make_float2(m, S);
            __syncthreads();
            if (tid < DQ) {
                float4 c4 = make_float4(0.f, 0.f, 0.f, 0.f);
                const float* ep = g_enc + ((size_t)b * SEQ + sb) * D + (tid << 2);
#pragma unroll 3
                for (int s = 0; s < 75; s++) {
                    float wv = s_w[s];
                    float4 e4 = ldcg4(ep + (size_t)s * D);
                    c4.x += wv * e4.x; c4.y += wv * e4.y;
                    c4.z += wv * e4.z; c4.w += wv * e4.w;
                }
                *(float4*)&g_ctxp[qtr][b * D + (tid << 2)] = c4;
            }
        }
        grid_barrier();
        // P3: gi = softmax-combined ctx @ resident decWc^T
        {
            // fill As3 = combined A (64 x 48), 3 float4/thread
            int am = tid & 63, kq0 = tid >> 6;
            float2 s0 = g_stat[am], s1 = g_stat[BS + am];
            float2 s2 = g_stat[2*BS + am], s3 = g_stat[3*BS + am];
            float M = fmaxf(fmaxf(s0.x, s1.x), fmaxf(s2.x, s3.x));
            float e0 = __expf(s0.x - M), e1 = __expf(s1.x - M);
            float e2 = __expf(s2.x - M), e3 = __expf(s3.x - M);
            float den = __fdividef(1.0f, s0.y*e0 + s1.y*e1 + s2.y*e2 + s3.y*e3);
            float al0 = e0*den, al1 = e1*den, al2 = e2*den, al3 = e3*den;
            const float* Ab = g_ctxp[0] + (size_t)am * D + kbeg3;
#pragma unroll
            for (int i = 0; i < 3; i++) {
                int kq = kq0 + 4 * i;
                float4 q0 = ldcg4(Ab + (kq << 2));
                float4 q1 = ldcg4(Ab + BS*D + (kq << 2));
                float4 q2 = ldcg4(Ab + 2*BS*D + (kq << 2));
                float4 q3 = ldcg4(Ab + 3*BS*D + (kq << 2));
                float4 v;
                v.x = al0*q0.x + al1*q1.x + al2*q2.x + al3*q3.x;
                v.y = al0*q0.y + al1*q1.y + al2*q2.y + al3*q3.y;
                v.z = al0*q0.z + al1*q1.z + al2*q2.z + al3*q3.z;
                v.w = al0*q0.w + al1*q1.w + al2*q2.w + al3*q3.w;
                Un[(kq*4+0)*68+am]=v.x; Un[(kq*4+1)*68+am]=v.y;
                Un[(kq*4+2)*68+am]=v.z; Un[(kq*4+3)*68+am]=v.w;
            }
            __syncthreads();
            gemm48_res(Un, Bs3, g_part + (size_t)kz3 * BS * G, G, n03);
        }
        grid_barrier();
        // P4: gate + prediction (64 blocks)
        if (bx < 64) {
            int b = bx;
            float last = (t == 0) ? 0.0f : __ldcg(&out[b * TSTEPS + t - 1]);
            float psum = 0.0f;
            if (tid < DQ) {
                int j = tid << 2;
                float4 s0 = make_float4(0.f,0.f,0.f,0.f), s1 = s0, s2 = s0;
                float4 u0 = s0, u1 = s0, u2 = s0;
#pragma unroll
                for (int z = 0; z < 16; z++) {
                    const float* P = g_part + (size_t)(z * BS + b) * G + j;
                    add4(s0, ldcg4(P)); add4(s1, ldcg4(P + D)); add4(s2, ldcg4(P + 2*D));
                }
#pragma unroll
                for (int z = 0; z < 12; z++) {
                    const float* Q = g_part2 + (size_t)(z * BS + b) * G + j;
                    add4(u0, ldcg4(Q)); add4(u1, ldcg4(Q + D)); add4(u2, ldcg4(Q + 2*D));
                }
                float4 w0 = *(const float4*)(g_decW0 + j);
                float4 w1 = *(const float4*)(g_decW0 + D + j);
                float4 w2 = *(const float4*)(g_decW0 + 2*D + j);
                float4 b0 = *(const float4*)(bih + j);
                float4 b1 = *(const float4*)(bih + D + j);
                float4 b2 = *(const float4*)(bih + 2*D + j);
                float4 c0 = *(const float4*)(bhh + j);
                float4 c1 = *(const float4*)(bhh + D + j);
                float4 c2 = *(const float4*)(bhh + 2*D + j);
                float4 hp = ldcg4(g_h + b * D + j);
                float4 tw = *(const float4*)(tW + j);
                float4 hn;
                float r, zt, n;
                r  = sigx(b0.x + last * w0.x + s0.x + c0.x + u0.x);
                zt = sigx(b1.x + last * w1.x + s1.x + c1.x + u1.x);
                n  = tanhx(b2.x + last * w2.x + s2.x + r * (c2.x + u2.x));
                hn.x = (1.f - zt) * n + zt * hp.x;
                r  = sigx(b0.y + last * w0.y + s0.y + c0.y + u0.y);
                zt = sigx(b1.y + last * w1.y + s1.y + c1.y + u1.y);
                n  = tanhx(b2.y + last * w2.y + s2.y + r * (c2.y + u2.y));
                hn.y = (1.f - zt) * n + zt * hp.y;
                r  = sigx(b0.z + last * w0.z + s0.z + c0.z + u0.z);
                zt = sigx(b1.z + last * w1.z + s1.z + c1.z + u1.z);
                n  = tanhx(b2.z + last * w2.z + s2.z + r * (c2.z + u2.z));
                hn.z = (1.f - zt) * n + zt * hp.z;
                r  = sigx(b0.w + last * w0.w + s0.w + c0.w + u0.w);
                zt = sigx(b1.w + last * w1.w + s1.w + c1.w + u1.w);
                n  = tanhx(b2.w + last * w2.w + s2.w + r * (c2.w + u2.w));
                hn.w = (1.f - zt) * n + zt * hp.w;
                *(float4*)(g_h + b * D + j) = hn;
                psum = tw.x * hn.x + tw.y * hn.y + tw.z * hn.z + tw.w * hn.w;
            }
            float tot = redSum(psum, red);
            if (tid == 0) out[b * TSTEPS + t] = tot + tb[0];
        }
        grid_barrier();
    }
}

extern "C" void kernel_launch(void* const* d_in, const int* in_sizes, int n_in,
                              void* d_out, int out_size) {
    const float* x       = (const float*)d_in[0];
    const float* enc_Wih = (const float*)d_in[1];
    const float* enc_Whh = (const float*)d_in[2];
    const float* enc_bih = (const float*)d_in[3];
    const float* enc_bhh = (const float*)d_in[4];
    const float* dec_Wih = (const float*)d_in[5];
    const float* dec_Whh = (const float*)d_in[6];
    const float* dec_bih = (const float*)d_in[7];
    const float* dec_bhh = (const float*)d_in[8];
    const float* qW      = (const float*)d_in[9];
    const float* qb      = (const float*)d_in[10];
    const float* mW      = (const float*)d_in[11];
    const float* mb      = (const float*)d_in[12];
    const float* pW      = (const float*)d_in[13];
    const float* pb      = (const float*)d_in[14];
    const float* tW      = (const float*)d_in[15];
    const float* tb      = (const float*)d_in[16];
    float* out = (float*)d_out;

    prep_kernel<<<(MTOT * D + 255) / 256, 256>>>(x, dec_Wih);
    sgemm_gi_kernel<<<dim3(G / 128, MTOT / 128), 256>>>(enc_Wih, enc_bih);
    encoder_kernel<<<NB, NT>>>(enc_Whh, enc_bhh);
    sgemm_mem_kernel<<<dim3(D / 128, MTOT / 128), 256>>>(mW, mb);
    decoder_kernel<<<NB, NT>>>(qW, qb, pW, pb, dec_Wih, dec_Whh,
                               dec_bih, dec_bhh, tW, tb, out);
}

// round 16
// speedup vs baseline: 1.3125x; 1.0089x over previous
#include <cuda_runtime.h>
#include <math.h>

typedef unsigned long long u64;
#define BS 64
#define SEQ 300
#define D 768
#define G 2304
#define TSTEPS 100
#define MTOT (BS*SEQ)
#define NB 288
#define NT 256
#define DQ (D/4)

__device__ __align__(16) float g_xpe[(size_t)MTOT*D];
__device__ __align__(16) float g_gi [(size_t)MTOT*G];
__device__ __align__(16) float g_enc[(size_t)MTOT*D];
__device__ __align__(16) float g_mem[(size_t)MTOT*D];
__device__ __align__(16) float g_pe[SEQ*D];
__device__ __align__(16) float g_h[BS*D];
__device__ __align__(16) float g_part [16*BS*G];
__device__ __align__(16) float g_part2[12*BS*G];
__device__ __align__(16) float g_qpart[12*BS*D];
__device__ __align__(16) float g_ctxp[4][BS*D];
__device__ __align__(16) float2 g_stat[4*BS];
__device__ __align__(16) float g_decWc[(size_t)G*D];
__device__ __align__(16) float g_decW0[G];
__device__ unsigned g_cnt[16*64];
__device__ unsigned g_root;
__device__ unsigned g_bar_gen;

__device__ __forceinline__ void grid_barrier() {
    __syncthreads();
    if (threadIdx.x == 0) {
        __threadfence();
        unsigned gen = *(volatile unsigned*)&g_bar_gen;
        unsigned leaf = (blockIdx.x & 15) << 6;
        if (atomicAdd(&g_cnt[leaf], 1u) == 17u) {
            if (atomicAdd(&g_root, 1u) == 15u) {
#pragma unroll
                for (int i = 0; i < 16; i++) *(volatile unsigned*)&g_cnt[i << 6] = 0u;
                *(volatile unsigned*)&g_root = 0u;
                __threadfence();
                *(volatile unsigned*)&g_bar_gen = gen + 1u;
            }
        }
        while (*(volatile unsigned*)&g_bar_gen == gen) { __nanosleep(32); }
    }
    __syncthreads();
}

__device__ __forceinline__ float sigx(float x)  { return __fdividef(1.0f, 1.0f + __expf(-x)); }
__device__ __forceinline__ float tanhx(float x) { return 1.0f - __fdividef(2.0f, __expf(2.0f*x) + 1.0f); }

__device__ __forceinline__ float4 ldcg4(const float* p) {
    return __ldcg(reinterpret_cast<const float4*>(p));
}
__device__ __forceinline__ void add4(float4& a, float4 b) {
    a.x += b.x; a.y += b.y; a.z += b.z; a.w += b.w;
}
__device__ __forceinline__ u64 dup2(float a) {
    u64 r; asm("mov.b64 %0, {%1, %1};" : "=l"(r) : "f"(a)); return r;
}
__device__ __forceinline__ u64 pack2(float a, float b) {
    u64 r; asm("mov.b64 %0, {%1, %2};" : "=l"(r) : "f"(a), "f"(b)); return r;
}
__device__ __forceinline__ u64 ffma2(u64 a, u64 b, u64 c) {
    u64 d; asm("fma.rn.f32x2 %0, %1, %2, %3;" : "=l"(d) : "l"(a), "l"(b), "l"(c)); return d;
}
__device__ __forceinline__ u64 mul2(u64 a, u64 b) {
    u64 d; asm("mul.rn.f32x2 %0, %1, %2;" : "=l"(d) : "l"(a), "l"(b)); return d;
}
__device__ __forceinline__ float2 unp2(u64 v) {
    float2 f; asm("mov.b64 {%0, %1}, %2;" : "=f"(f.x), "=f"(f.y) : "l"(v)); return f;
}
__device__ __forceinline__ float4 f4of(u64 a, u64 b) {
    float4 v;
    asm("mov.b64 {%0, %1}, %2;" : "=f"(v.x), "=f"(v.y) : "l"(a));
    asm("mov.b64 {%0, %1}, %2;" : "=f"(v.z), "=f"(v.w) : "l"(b));
    return v;
}

#define TANH2(res, xin) do { \
    u64 _x = (xin); \
    u64 _x2 = mul2(_x, _x); \
    u64 _p = ffma2(_x2, tC0, tC1); \
    _p = ffma2(_x2, _p, tC2); \
    _p = ffma2(_x2, _p, tC3); \
    _p = ffma2(_x2, _p, tC4); \
    _p = ffma2(_x2, _p, tC5); \
    _p = ffma2(_x2, _p, tC6); \
    u64 _q = ffma2(_x2, tQ0, tQ1); \
    _q = ffma2(_x2, _q, tQ2); \
    _q = ffma2(_x2, _q, tQ3); \
    u64 _num = mul2(_x, _p); \
    float2 _qf = unp2(_q); \
    u64 _r = pack2(__uint_as_float(0x7EF477D5u - __float_as_uint(_qf.x)), \
                   __uint_as_float(0x7EF477D5u - __float_as_uint(_qf.y))); \
    u64 _nq = _q ^ 0x8000000080000000ULL; \
    _r = mul2(_r, ffma2(_nq, _r, tTWO)); \
    _r = mul2(_r, ffma2(_nq, _r, tTWO)); \
    _r = mul2(_r, ffma2(_nq, _r, tTWO)); \
    (res) = mul2(_num, _r); \
} while (0)

__device__ __forceinline__ float clampt(float x) {
    return fminf(fmaxf(x, -7.90531110763549805f), 7.90531110763549805f);
}

__device__ __forceinline__ float redSum(float v, float* red) {
    __syncthreads();
    int lane = threadIdx.x & 31, w = threadIdx.x >> 5;
#pragma unroll
    for (int o = 16; o; o >>= 1) v += __shfl_down_sync(0xffffffffu, v, o);
    if (lane == 0) red[w] = v;
    __syncthreads();
    if (w == 0) {
        float r = (lane < 8) ? red[lane] : 0.0f;
#pragma unroll
        for (int o = 4; o; o >>= 1) r += __shfl_down_sync(0xffffffffu, r, o);
        if (lane == 0) red[0] = r;
    }
    __syncthreads();
    return red[0];
}
__device__ __forceinline__ float redMax(float v, float* red) {
    __syncthreads();
    int lane = threadIdx.x & 31, w = threadIdx.x >> 5;
#pragma unroll
    for (int o = 16; o; o >>= 1) v = fmaxf(v, __shfl_down_sync(0xffffffffu, v, o));
    if (lane == 0) red[w] = v;
    __syncthreads();
    if (w == 0) {
        float r = (lane < 8) ? red[lane] : -1e30f;
#pragma unroll
        for (int o = 4; o; o >>= 1) r = fmaxf(r, __shfl_down_sync(0xffffffffu, r, o));
        if (lane == 0) red[0] = r;
    }
    __syncthreads();
    return red[0];
}

#define FF8(i, aval) do { u64 ad_ = dup2(aval); \
    acc[i][0] = ffma2(ad_, b01.x, acc[i][0]); \
    acc[i][1] = ffma2(ad_, b01.y, acc[i][1]); \
    acc[i][2] = ffma2(ad_, b23.x, acc[i][2]); \
    acc[i][3] = ffma2(ad_, b23.y, acc[i][3]); } while (0)

// ---- resident compute: nkk K-steps from smem As[nkk][68], Bs[nkk][132] ----
__device__ __forceinline__ void gemm_res(const float* __restrict__ As,
                                         const float* __restrict__ Bs,
                                         int nkk, float* __restrict__ Cp,
                                         int ldc, int n0)
{
    const int tid = threadIdx.x;
    if (tid >= 128) return;
    const int ty = tid >> 4, tx = tid & 15;
    u64 acc[8][4];
#pragma unroll
    for (int i = 0; i < 8; i++)
#pragma unroll
        for (int j = 0; j < 4; j++) acc[i][j] = 0ull;
    for (int k0 = 0; k0 < nkk; k0 += 8) {
#pragma unroll
        for (int k2 = 0; k2 < 8; k2++) {
            int kk = k0 + k2;
            float4 a0 = *(const float4*)(As + kk*68 + ty*4);
            float4 a1 = *(const float4*)(As + kk*68 + 32 + ty*4);
            ulonglong2 b01 = *(const ulonglong2*)(Bs + kk*132 + tx*4);
            ulonglong2 b23 = *(const ulonglong2*)(Bs + kk*132 + 64 + tx*4);
            FF8(0, a0.x); FF8(1, a0.y); FF8(2, a0.z); FF8(3, a0.w);
            FF8(4, a1.x); FF8(5, a1.y); FF8(6, a1.z); FF8(7, a1.w);
        }
    }
#pragma unroll
    for (int i = 0; i < 8; i++) {
        int r = (i < 4) ? (ty*4 + i) : (32 + ty*4 + (i - 4));
        float* cr = Cp + (size_t)r * ldc + n0;
        *(float4*)(cr + tx*4)      = f4of(acc[i][0], acc[i][1]);
        *(float4*)(cr + 64 + tx*4) = f4of(acc[i][2], acc[i][3]);
    }
}

// ---- big GEMM (f32x2, 128x128 tile): C = A @ B^T + bias ----
__device__ __forceinline__ void sgemm_f2_body(const float* __restrict__ A,
                                              const float* __restrict__ B,
                                              const float* __restrict__ bias,
                                              float* __restrict__ C, int N, int K)
{
    __shared__ __align__(16) float As[2112];
    __shared__ __align__(16) float Bs[2112];
    const int tid = threadIdx.x, ty = tid >> 4, tx = tid & 15;
    const int m0 = blockIdx.y << 7, n0 = blockIdx.x << 7;
    const int lm = tid & 127, lkq = tid >> 7;
    u64 acc[8][4];
#pragma unroll
    for (int i = 0; i < 8; i++)
#pragma unroll
        for (int j = 0; j < 4; j++) acc[i][j] = 0ull;
    const float* Ap = A + (size_t)(m0 + lm) * K + lkq * 4;
    const float* Bp = B + (size_t)(n0 + lm) * K + lkq * 4;
    const int nst = K >> 3;
    float4 va = *(const float4*)Ap, vb = *(const float4*)Bp;
    As[(lkq*4+0)*132+lm]=va.x; As[(lkq*4+1)*132+lm]=va.y;
    As[(lkq*4+2)*132+lm]=va.z; As[(lkq*4+3)*132+lm]=va.w;
    Bs[(lkq*4+0)*132+lm]=vb.x; Bs[(lkq*4+1)*132+lm]=vb.y;
    Bs[(lkq*4+2)*132+lm]=vb.z; Bs[(lkq*4+3)*132+lm]=vb.w;
    __syncthreads();
    for (int st = 0; st < nst; st++) {
        if (st + 1 < nst) {
            va = *(const float4*)(Ap + (st+1)*8);
            vb = *(const float4*)(Bp + (st+1)*8);
        }
        const float* Asl = As + (st & 1) * 1056;
        const float* Bsl = Bs + (st & 1) * 1056;
#pragma unroll
        for (int kk = 0; kk < 8; kk++) {
            float4 a0 = *(const float4*)(Asl + kk*132 + ty*4);
            float4 a1 = *(const float4*)(Asl + kk*132 + 64 + ty*4);
            ulonglong2 b01 = *(const ulonglong2*)(Bsl + kk*132 + tx*4);
            ulonglong2 b23 = *(const ulonglong2*)(Bsl + kk*132 + 64 + tx*4);
            FF8(0, a0.x); FF8(1, a0.y); FF8(2, a0.z); FF8(3, a0.w);
            FF8(4, a1.x); FF8(5, a1.y); FF8(6, a1.z); FF8(7, a1.w);
        }
        if (st + 1 < nst) {
            float* An = As + ((st+1) & 1) * 1056;
            float* Bn = Bs + ((st+1) & 1) * 1056;
            An[(lkq*4+0)*132+lm]=va.x; An[(lkq*4+1)*132+lm]=va.y;
            An[(lkq*4+2)*132+lm]=va.z; An[(lkq*4+3)*132+lm]=va.w;
            Bn[(lkq*4+0)*132+lm]=vb.x; Bn[(lkq*4+1)*132+lm]=vb.y;
            Bn[(lkq*4+2)*132+lm]=vb.z; Bn[(lkq*4+3)*132+lm]=vb.w;
            __syncthreads();
        }
    }
    const int c0 = n0 + tx*4, c1 = n0 + 64 + tx*4;
    float4 bi0 = *(const float4*)(bias + c0);
    float4 bi1 = *(const float4*)(bias + c1);
#pragma unroll
    for (int i = 0; i < 8; i++) {
        int r = m0 + ((i < 4) ? (ty*4 + i) : (64 + ty*4 + i - 4));
        float4 v0 = f4of(acc[i][0], acc[i][1]);
        float4 v1 = f4of(acc[i][2], acc[i][3]);
        v0.x += bi0.x; v0.y += bi0.y; v0.z += bi0.z; v0.w += bi0.w;
        v1.x += bi1.x; v1.y += bi1.y; v1.z += bi1.z; v1.w += bi1.w;
        *(float4*)(C + (size_t)r * N + c0) = v0;
        *(float4*)(C + (size_t)r * N + c1) = v1;
    }
}

__global__ __launch_bounds__(256, 2) void sgemm_gi_kernel(const float* __restrict__ W,
                                                          const float* __restrict__ bias) {
    sgemm_f2_body(g_xpe, W, bias, g_gi, G, D);
}
__global__ __launch_bounds__(256, 2) void sgemm_mem_kernel(const float* __restrict__ W,
                                                           const float* __restrict__ bias) {
    sgemm_f2_body(g_enc, W, bias, g_mem, D, D);
}

// PE table: 230K elements (MUFU work done once, not 14.7M times)
__global__ void pe_kernel(const float* __restrict__ dWih) {
    int idx = blockIdx.x * blockDim.x + threadIdx.x;
    if (idx < SEQ * D) {
        int k = idx % D, s = idx / D;
        const float c = 9.210340371976184f / (float)D;
        float dv  = expf(-(float)(k & ~1) * c);
        float arg = (float)s * dv;
        g_pe[idx] = (k & 1) ? cosf(arg) : sinf(arg);
    }
    if (idx < G) g_decW0[idx] = dWih[(size_t)idx * (D + 1)];
    if (idx < BS * D) g_h[idx] = 0.0f;
}

__global__ void prep_kernel(const float* __restrict__ x, const float* __restrict__ dWih) {
    size_t i4 = (size_t)blockIdx.x * blockDim.x + threadIdx.x;
    if (i4 < (size_t)MTOT * D / 4) {
        float4 v = ldcg4(x + i4 * 4);
        float4 p = *(const float4*)(g_pe + (i4 % (SEQ * D / 4)) * 4);
        add4(v, p);
        *(float4*)(g_xpe + i4 * 4) = v;
    }
    if (i4 < (size_t)G * D / 4) {
        int g = (int)(i4 * 4 / D), k = (int)(i4 * 4 % D);
        const float* src = dWih + (size_t)g * (D + 1) + 1 + k;
        float4 v = make_float4(src[0], src[1], src[2], src[3]);
        *(float4*)(g_decWc + i4 * 4) = v;
    }
}

// ---- persistent encoder: resident Whh slice, 18nt x 16kz = 288 blocks ----
__global__ __launch_bounds__(NT, 2) void encoder_kernel(const float* __restrict__ Whh,
                                                        const float* __restrict__ bhh)
{
    __shared__ __align__(16) float Bs[48*132];
    __shared__ __align__(16) float As[48*68];
    const int bx = blockIdx.x, tid = threadIdx.x;
    const int nt = bx >> 4, kz = bx & 15;
    const int n0 = nt << 7, kbeg = kz * 48;
    float* Cp = g_part + (size_t)kz * BS * G;
    {
        int bn = tid & 127, kq0 = tid >> 7;
#pragma unroll
        for (int i = 0; i < 6; i++) {
            int kq = kq0 + 2 * i;
            float4 v = ldcg4(Whh + (size_t)(n0 + bn) * D + kbeg + (kq << 2));
            Bs[(kq*4+0)*132+bn]=v.x; Bs[(kq*4+1)*132+bn]=v.y;
            Bs[(kq*4+2)*132+bn]=v.z; Bs[(kq*4+3)*132+bn]=v.w;
        }
    }
    const int am = tid & 63, kq0 = tid >> 6;
    const int chunk = (bx < 192) ? 43 : 42;
    const int start = bx * 42 + ((bx < 192) ? bx : 192);
    const int gitem = (tid < chunk) ? (start + tid) : -1;
    const int gb = (gitem >= 0) ? (gitem / DQ) : 0;
    const int gj = (gitem >= 0) ? ((gitem - gb * DQ) << 2) : 0;
    grid_barrier();

    for (int s = 0; s < SEQ; s++) {
#pragma unroll
        for (int i = 0; i < 3; i++) {
            int kq = kq0 + 4 * i;
            float4 v = ldcg4(g_h + (size_t)am * D + kbeg + (kq << 2));
            As[(kq*4+0)*68+am]=v.x; As[(kq*4+1)*68+am]=v.y;
            As[(kq*4+2)*68+am]=v.z; As[(kq*4+3)*68+am]=v.w;
        }
        __syncthreads();
        gemm_res(As, Bs, 48, Cp, G, n0);
        grid_barrier();
        if (gitem >= 0) {
            float4 t0 = make_float4(0.f,0.f,0.f,0.f), t1 = t0, t2 = t0;
#pragma unroll
            for (int z = 0; z < 16; z++) {
                const float* P = g_part + (size_t)(z * BS + gb) * G + gj;
                add4(t0, ldcg4(P)); add4(t1, ldcg4(P + D)); add4(t2, ldcg4(P + 2*D));
            }
            const float* gip = g_gi + ((size_t)gb * SEQ + s) * G + gj;
            float4 gr = ldcg4(gip), gz = ldcg4(gip + D), gn = ldcg4(gip + 2*D);
            float4 br = *(const float4*)(bhh + gj);
            float4 bz = *(const float4*)(bhh + D + gj);
            float4 bn = *(const float4*)(bhh + 2*D + gj);
            float4 hp = ldcg4(g_h + gb * D + gj);
            float4 hn;
            float r, zt, n;
            r = sigx(gr.x + br.x + t0.x); zt = sigx(gz.x + bz.x + t1.x);
            n = tanhx(gn.x + r * (bn.x + t2.x)); hn.x = (1.f - zt) * n + zt * hp.x;
            r = sigx(gr.y + br.y + t0.y); zt = sigx(gz.y + bz.y + t1.y);
            n = tanhx(gn.y + r * (bn.y + t2.y)); hn.y = (1.f - zt) * n + zt * hp.y;
            r = sigx(gr.z + br.z + t0.z); zt = sigx(gz.z + bz.z + t1.z);
            n = tanhx(gn.z + r * (bn.z + t2.z)); hn.z = (1.f - zt) * n + zt * hp.z;
            r = sigx(gr.w + br.w + t0.w); zt = sigx(gz.w + bz.w + t1.w);
            n = tanhx(gn.w + r * (bn.w + t2.w)); hn.w = (1.f - zt) * n + zt * hp.w;
            *(float4*)(g_h + gb * D + gj) = hn;
            *(float4*)(g_enc + ((size_t)gb * SEQ + s) * D + gj) = hn;
        }
        grid_barrier();
    }
}

// ---- persistent decoder: dynamic smem, resident B for P1 AND P3 ----
// dyn layout: Bs1[64*132]=8448 | Bs3[48*132]=6336 | As[64*68]=4352  (76.5 KB)
__global__ __launch_bounds__(NT, 2) void decoder_kernel(
    const float* __restrict__ qW,  const float* __restrict__ qb,
    const float* __restrict__ pW,  const float* __restrict__ pb,
    const float* __restrict__ dWih, const float* __restrict__ dWhh,
    const float* __restrict__ bih, const float* __restrict__ bhh,
    const float* __restrict__ tW,  const float* __restrict__ tb,
    float* __restrict__ out)
{
    extern __shared__ __align__(16) float dynsm[];
    float* Bs1 = dynsm;
    float* Bs3 = dynsm + 64*132;
    float* As  = dynsm + 64*132 + 48*132;
    __shared__ __align__(16) float s_q[D];
    __shared__ __align__(16) float s_pw[D];
    __shared__ float s_w[80];
    __shared__ float red[8];
    const int bx = blockIdx.x, tid = threadIdx.x;
    // P1 mapping
    const int nt1 = bx / 12, kz1 = bx % 12;
    const int kbeg1 = kz1 * 64;
    const float* B1src; float* Cp1; int n01, ldc1;
    if (nt1 < 6) { B1src = qW;   n01 = nt1 << 7;       Cp1 = g_qpart + (size_t)kz1 * BS * D; ldc1 = D; }
    else         { B1src = dWhh; n01 = (nt1 - 6) << 7; Cp1 = g_part2 + (size_t)kz1 * BS * G; ldc1 = G; }
    // P3 mapping
    const int nt3 = bx >> 4, kz3 = bx & 15;
    const int n03 = nt3 << 7, kbeg3 = kz3 * 48;
    // resident fills
    {
        int bn = tid & 127, kq0 = tid >> 7;
#pragma unroll
        for (int i = 0; i < 8; i++) {           // P1 B: 64 kk
            int kq = kq0 + 2 * i;
            float4 v = ldcg4(B1src + (size_t)(n01 + bn) * D + kbeg1 + (kq << 2));
            Bs1[(kq*4+0)*132+bn]=v.x; Bs1[(kq*4+1)*132+bn]=v.y;
            Bs1[(kq*4+2)*132+bn]=v.z; Bs1[(kq*4+3)*132+bn]=v.w;
        }
#pragma unroll
        for (int i = 0; i < 6; i++) {           // P3 B: 48 kk
            int kq = kq0 + 2 * i;
            float4 v = ldcg4(g_decWc + (size_t)(n03 + bn) * D + kbeg3 + (kq << 2));
            Bs3[(kq*4+0)*132+bn]=v.x; Bs3[(kq*4+1)*132+bn]=v.y;
            Bs3[(kq*4+2)*132+bn]=v.z; Bs3[(kq*4+3)*132+bn]=v.w;
        }
    }
    {
        int idx = bx * NT + tid;
        if (idx < BS * D) g_h[idx] = 0.0f;
    }
    grid_barrier();

    for (int t = 0; t < TSTEPS; t++) {
        // P1: fill A (h slice 64x64), then resident 64-kk GEMM
        {
            int am = tid & 63, kq0 = tid >> 6;
#pragma unroll
            for (int i = 0; i < 4; i++) {
                int kq = kq0 + 4 * i;
                float4 v = ldcg4(g_h + (size_t)am * D + kbeg1 + (kq << 2));
                As[(kq*4+0)*68+am]=v.x; As[(kq*4+1)*68+am]=v.y;
                As[(kq*4+2)*68+am]=v.z; As[(kq*4+3)*68+am]=v.w;
            }
            __syncthreads();
            gemm_res(As, Bs1, 64, Cp1, ldc1, n01);
        }
        grid_barrier();
        // P2: logits + local softmax + unnormalized quarter-context (256 blocks)
        if (bx < 256) {
            int b = bx >> 2, qtr = bx & 3;
            int sb = qtr * 75;
            if (tid < DQ) {
                int j = tid << 2;
                float4 v = *(const float4*)(qb + j);
#pragma unroll
                for (int z = 0; z < 12; z++)
                    add4(v, ldcg4(g_qpart + (size_t)(z * BS + b) * D + j));
                *(float4*)&s_q[j]  = v;
                *(float4*)&s_pw[j] = *(const float4*)(pW + j);
            }
            __syncthreads();
            const u64 tC0 = dup2(-2.76076847742355e-16f), tC1 = dup2(2.00018790482477e-13f);
            const u64 tC2 = dup2(-8.60467152213735e-11f), tC3 = dup2(5.12229709037114e-08f);
            const u64 tC4 = dup2(1.48572235717979e-05f),  tC5 = dup2(6.37261928875436e-04f);
            const u64 tC6 = dup2(4.89352455891786e-03f);
            const u64 tQ0 = dup2(1.19825839466702e-06f),  tQ1 = dup2(1.18534705686654e-04f);
            const u64 tQ2 = dup2(2.26843463243900e-03f),  tQ3 = dup2(4.89352518554385e-03f);
            const u64 tTWO = dup2(2.0f);
            int w = tid >> 5, lane = tid & 31;
            for (int s = w; s < 75; s += 8) {
                const float* mrow = g_mem + ((size_t)b * SEQ + sb + s) * D;
                u64 acc2 = 0ull;
#pragma unroll
                for (int it = 0; it < 6; it++) {
                    int k = (lane << 2) + it * 128;
                    float4 m4 = ldcg4(mrow + k);
                    float4 q4 = *(const float4*)&s_q[k];
                    u64 xa = pack2(clampt(m4.x + q4.x), clampt(m4.y + q4.y));
                    u64 xb = pack2(clampt(m4.z + q4.z), clampt(m4.w + q4.w));
                    u64 ta, tb2;
                    TANH2(ta, xa);
                    TANH2(tb2, xb);
                    ulonglong2 w2 = *(const ulonglong2*)&s_pw[k];
                    acc2 = ffma2(w2.x, ta, acc2);
                    acc2 = ffma2(w2.y, tb2, acc2);
                }
                float2 af = unp2(acc2);
                float acc = af.x + af.y;
#pragma unroll
                for (int o = 16; o; o >>= 1) acc += __shfl_down_sync(0xffffffffu, acc, o);
                if (lane == 0) s_w[s] = acc;
            }
            float lv = (tid < 75) ? s_w[tid] : -1e30f;
            float m = redMax(lv, red);
            float ev = (tid < 75) ? __expf(s_w[tid] - m) : 0.0f;
            float S = redSum(ev, red);
            if (tid < 75) s_w[tid] = ev;
            if (tid == 0) g_stat[qtr * BS + b] = make_float2(m, S);
            __syncthreads();
            if (tid < DQ) {
                float4 c4 = make_float4(0.f, 0.f, 0.f, 0.f);
                const float* ep = g_enc + ((size_t)b * SEQ + sb) * D + (tid << 2);
#pragma unroll 3
                for (int s = 0; s < 75; s++) {
                    float wv = s_w[s];
                    float4 e4 = ldcg4(ep + (size_t)s * D);
                    c4.x += wv * e4.x; c4.y += wv * e4.y;
                    c4.z += wv * e4.z; c4.w += wv * e4.w;
                }
                *(float4*)&g_ctxp[qtr][b * D + (tid << 2)] = c4;
            }
        }
        grid_barrier();
        // P3: fill A = softmax-combined ctx (64x48), resident 48-kk GEMM
        {
            int am = tid & 63, kq0 = tid >> 6;
            float2 s0 = g_stat[am], s1 = g_stat[BS + am];
            float2 s2 = g_stat[2*BS + am], s3 = g_stat[3*BS + am];
            float M = fmaxf(fmaxf(s0.x, s1.x), fmaxf(s2.x, s3.x));
            float e0 = __expf(s0.x - M), e1 = __expf(s1.x - M);
            float e2 = __expf(s2.x - M), e3 = __expf(s3.x - M);
            float den = __fdividef(1.0f, s0.y*e0 + s1.y*e1 + s2.y*e2 + s3.y*e3);
            float al0 = e0*den, al1 = e1*den, al2 = e2*den, al3 = e3*den;
            const float* Ab = g_ctxp[0] + (size_t)am * D + kbeg3;
#pragma unroll
            for (int i = 0; i < 3; i++) {
                int kq = kq0 + 4 * i;
                float4 q0 = ldcg4(Ab + (kq << 2));
                float4 q1 = ldcg4(Ab + BS*D + (kq << 2));
                float4 q2 = ldcg4(Ab + 2*BS*D + (kq << 2));
                float4 q3 = ldcg4(Ab + 3*BS*D + (kq << 2));
                float4 v;
                v.x = al0*q0.x + al1*q1.x + al2*q2.x + al3*q3.x;
                v.y = al0*q0.y + al1*q1.y + al2*q2.y + al3*q3.y;
                v.z = al0*q0.z + al1*q1.z + al2*q2.z + al3*q3.z;
                v.w = al0*q0.w + al1*q1.w + al2*q2.w + al3*q3.w;
                As[(kq*4+0)*68+am]=v.x; As[(kq*4+1)*68+am]=v.y;
                As[(kq*4+2)*68+am]=v.z; As[(kq*4+3)*68+am]=v.w;
            }
            __syncthreads();
            gemm_res(As, Bs3, 48, g_part + (size_t)kz3 * BS * G, G, n03);
        }
        grid_barrier();
        // P4: gate + prediction (64 blocks)
        if (bx < 64) {
            int b = bx;
            float last = (t == 0) ? 0.0f : __ldcg(&out[b * TSTEPS + t - 1]);
            float psum = 0.0f;
            if (tid < DQ) {
                int j = tid << 2;
                float4 s0 = make_float4(0.f,0.f,0.f,0.f), s1 = s0, s2 = s0;
                float4 u0 = s0, u1 = s0, u2 = s0;
#pragma unroll
                for (int z = 0; z < 16; z++) {
                    const float* P = g_part + (size_t)(z * BS + b) * G + j;
                    add4(s0, ldcg4(P)); add4(s1, ldcg4(P + D)); add4(s2, ldcg4(P + 2*D));
                }
#pragma unroll
                for (int z = 0; z < 12; z++) {
                    const float* Q = g_part2 + (size_t)(z * BS + b) * G + j;
                    add4(u0, ldcg4(Q)); add4(u1, ldcg4(Q + D)); add4(u2, ldcg4(Q + 2*D));
                }
                float4 w0 = *(const float4*)(g_decW0 + j);
                float4 w1 = *(const float4*)(g_decW0 + D + j);
                float4 w2 = *(const float4*)(g_decW0 + 2*D + j);
                float4 b0 = *(const float4*)(bih + j);
                float4 b1 = *(const float4*)(bih + D + j);
                float4 b2 = *(const float4*)(bih + 2*D + j);
                float4 c0 = *(const float4*)(bhh + j);
                float4 c1 = *(const float4*)(bhh + D + j);
                float4 c2 = *(const float4*)(bhh + 2*D + j);
                float4 hp = ldcg4(g_h + b * D + j);
                float4 tw = *(const float4*)(tW + j);
                float4 hn;
                float r, zt, n;
                r  = sigx(b0.x + last * w0.x + s0.x + c0.x + u0.x);
                zt = sigx(b1.x + last * w1.x + s1.x + c1.x + u1.x);
                n  = tanhx(b2.x + last * w2.x + s2.x + r * (c2.x + u2.x));
                hn.x = (1.f - zt) * n + zt * hp.x;
                r  = sigx(b0.y + last * w0.y + s0.y + c0.y + u0.y);
                zt = sigx(b1.y + last * w1.y + s1.y + c1.y + u1.y);
                n  = tanhx(b2.y + last * w2.y + s2.y + r * (c2.y + u2.y));
                hn.y = (1.f - zt) * n + zt * hp.y;
                r  = sigx(b0.z + last * w0.z + s0.z + c0.z + u0.z);
                zt = sigx(b1.z + last * w1.z + s1.z + c1.z + u1.z);
                n  = tanhx(b2.z + last * w2.z + s2.z + r * (c2.z + u2.z));
                hn.z = (1.f - zt) * n + zt * hp.z;
                r  = sigx(b0.w + last * w0.w + s0.w + c0.w + u0.w);
                zt = sigx(b1.w + last * w1.w + s1.w + c1.w + u1.w);
                n  = tanhx(b2.w + last * w2.w + s2.w + r * (c2.w + u2.w));
                hn.w = (1.f - zt) * n + zt * hp.w;
                *(float4*)(g_h + b * D + j) = hn;
                psum = tw.x * hn.x + tw.y * hn.y + tw.z * hn.z + tw.w * hn.w;
            }
            float tot = redSum(psum, red);
            if (tid == 0) out[b * TSTEPS + t] = tot + tb[0];
        }
        grid_barrier();
    }
}

#define DEC_DYNSM ((64*132 + 48*132 + 64*68) * (int)sizeof(float))

extern "C" void kernel_launch(void* const* d_in, const int* in_sizes, int n_in,
                              void* d_out, int out_size) {
    const float* x       = (const float*)d_in[0];
    const float* enc_Wih = (const float*)d_in[1];
    const float* enc_Whh = (const float*)d_in[2];
    const float* enc_bih = (const float*)d_in[3];
    const float* enc_bhh = (const float*)d_in[4];
    const float* dec_Wih = (const float*)d_in[5];
    const float* dec_Whh = (const float*)d_in[6];
    const float* dec_bih = (const float*)d_in[7];
    const float* dec_bhh = (const float*)d_in[8];
    const float* qW      = (const float*)d_in[9];
    const float* qb      = (const float*)d_in[10];
    const float* mW      = (const float*)d_in[11];
    const float* mb      = (const float*)d_in[12];
    const float* pW      = (const float*)d_in[13];
    const float* pb      = (const float*)d_in[14];
    const float* tW      = (const float*)d_in[15];
    const float* tb      = (const float*)d_in[16];
    float* out = (float*)d_out;

    static int smem_set = 0;
    if (!smem_set) {
        cudaFuncSetAttribute(decoder_kernel,
                             cudaFuncAttributeMaxDynamicSharedMemorySize, DEC_DYNSM);
        smem_set = 1;
    }

    pe_kernel<<<(SEQ * D + 255) / 256, 256>>>(dec_Wih);
    prep_kernel<<<(MTOT * D / 4 + 255) / 256, 256>>>(x, dec_Wih);
    sgemm_gi_kernel<<<dim3(G / 128, MTOT / 128), 256>>>(enc_Wih, enc_bih);
    encoder_kernel<<<NB, NT>>>(enc_Whh, enc_bhh);
    sgemm_mem_kernel<<<dim3(D / 128, MTOT / 128), 256>>>(mW, mb);
    decoder_kernel<<<NB, NT, DEC_DYNSM>>>(qW, qb, pW, pb, dec_Wih, dec_Whh,
                                          dec_bih, dec_bhh, tW, tb, out);
}

// round 17
// speedup vs baseline: 1.3693x; 1.0433x over previous
#include <cuda_runtime.h>
#include <math.h>

typedef unsigned long long u64;
#define BS 64
#define SEQ 300
#define D 768
#define G 2304
#define TSTEPS 100
#define MTOT (BS*SEQ)
#define NB 288
#define NT 256
#define DQ (D/4)

__device__ __align__(16) float g_xpe[(size_t)MTOT*D];
__device__ __align__(16) float g_gi [(size_t)MTOT*G];
__device__ __align__(16) float g_enc[(size_t)MTOT*D];
__device__ __align__(16) float g_mem[(size_t)MTOT*D];
__device__ __align__(16) float g_pe[SEQ*D];
__device__ __align__(16) float g_h[BS*D];
__device__ __align__(16) float g_part [16*BS*G];
__device__ __align__(16) float g_part2[12*BS*G];
__device__ __align__(16) float g_qpart[12*BS*D];
__device__ __align__(16) float g_ctxp[4][BS*D];
__device__ __align__(16) float2 g_stat[4*BS];
__device__ __align__(16) float g_decWc[(size_t)G*D];
__device__ __align__(16) float g_decW0[G];
__device__ unsigned g_cnt[16*64];
__device__ unsigned g_root;
__device__ unsigned g_bar_gen;

__device__ __forceinline__ void grid_barrier() {
    __syncthreads();
    if (threadIdx.x == 0) {
        __threadfence();
        unsigned gen = *(volatile unsigned*)&g_bar_gen;
        unsigned leaf = (blockIdx.x & 15) << 6;
        if (atomicAdd(&g_cnt[leaf], 1u) == 17u) {
            if (atomicAdd(&g_root, 1u) == 15u) {
#pragma unroll
                for (int i = 0; i < 16; i++) *(volatile unsigned*)&g_cnt[i << 6] = 0u;
                *(volatile unsigned*)&g_root = 0u;
                __threadfence();
                *(volatile unsigned*)&g_bar_gen = gen + 1u;
            }
        }
        while (*(volatile unsigned*)&g_bar_gen == gen) { __nanosleep(32); }
    }
    __syncthreads();
}

__device__ __forceinline__ float sigx(float x)  { return __fdividef(1.0f, 1.0f + __expf(-x)); }
__device__ __forceinline__ float tanhx(float x) { return 1.0f - __fdividef(2.0f, __expf(2.0f*x) + 1.0f); }

__device__ __forceinline__ float4 ldcg4(const float* p) {
    return __ldcg(reinterpret_cast<const float4*>(p));
}
__device__ __forceinline__ void add4(float4& a, float4 b) {
    a.x += b.x; a.y += b.y; a.z += b.z; a.w += b.w;
}
__device__ __forceinline__ u64 dup2(float a) {
    u64 r; asm("mov.b64 %0, {%1, %1};" : "=l"(r) : "f"(a)); return r;
}
__device__ __forceinline__ u64 pack2(float a, float b) {
    u64 r; asm("mov.b64 %0, {%1, %2};" : "=l"(r) : "f"(a), "f"(b)); return r;
}
__device__ __forceinline__ u64 ffma2(u64 a, u64 b, u64 c) {
    u64 d; asm("fma.rn.f32x2 %0, %1, %2, %3;" : "=l"(d) : "l"(a), "l"(b), "l"(c)); return d;
}
__device__ __forceinline__ u64 mul2(u64 a, u64 b) {
    u64 d; asm("mul.rn.f32x2 %0, %1, %2;" : "=l"(d) : "l"(a), "l"(b)); return d;
}
__device__ __forceinline__ float2 unp2(u64 v) {
    float2 f; asm("mov.b64 {%0, %1}, %2;" : "=f"(f.x), "=f"(f.y) : "l"(v)); return f;
}
__device__ __forceinline__ float4 f4of(u64 a, u64 b) {
    float4 v;
    asm("mov.b64 {%0, %1}, %2;" : "=f"(v.x), "=f"(v.y) : "l"(a));
    asm("mov.b64 {%0, %1}, %2;" : "=f"(v.z), "=f"(v.w) : "l"(b));
    return v;
}

#define TANH2(res, xin) do { \
    u64 _x = (xin); \
    u64 _x2 = mul2(_x, _x); \
    u64 _p = ffma2(_x2, tC0, tC1); \
    _p = ffma2(_x2, _p, tC2); \
    _p = ffma2(_x2, _p, tC3); \
    _p = ffma2(_x2, _p, tC4); \
    _p = ffma2(_x2, _p, tC5); \
    _p = ffma2(_x2, _p, tC6); \
    u64 _q = ffma2(_x2, tQ0, tQ1); \
    _q = ffma2(_x2, _q, tQ2); \
    _q = ffma2(_x2, _q, tQ3); \
    u64 _num = mul2(_x, _p); \
    float2 _qf = unp2(_q); \
    u64 _r = pack2(__uint_as_float(0x7EF477D5u - __float_as_uint(_qf.x)), \
                   __uint_as_float(0x7EF477D5u - __float_as_uint(_qf.y))); \
    u64 _nq = _q ^ 0x8000000080000000ULL; \
    _r = mul2(_r, ffma2(_nq, _r, tTWO)); \
    _r = mul2(_r, ffma2(_nq, _r, tTWO)); \
    _r = mul2(_r, ffma2(_nq, _r, tTWO)); \
    (res) = mul2(_num, _r); \
} while (0)

__device__ __forceinline__ float clampt(float x) {
    return fminf(fmaxf(x, -7.90531110763549805f), 7.90531110763549805f);
}

__device__ __forceinline__ float redSum(float v, float* red) {
    __syncthreads();
    int lane = threadIdx.x & 31, w = threadIdx.x >> 5;
#pragma unroll
    for (int o = 16; o; o >>= 1) v += __shfl_down_sync(0xffffffffu, v, o);
    if (lane == 0) red[w] = v;
    __syncthreads();
    if (w == 0) {
        float r = (lane < 8) ? red[lane] : 0.0f;
#pragma unroll
        for (int o = 4; o; o >>= 1) r += __shfl_down_sync(0xffffffffu, r, o);
        if (lane == 0) red[0] = r;
    }
    __syncthreads();
    return red[0];
}
__device__ __forceinline__ float redMax(float v, float* red) {
    __syncthreads();
    int lane = threadIdx.x & 31, w = threadIdx.x >> 5;
#pragma unroll
    for (int o = 16; o; o >>= 1) v = fmaxf(v, __shfl_down_sync(0xffffffffu, v, o));
    if (lane == 0) red[w] = v;
    __syncthreads();
    if (w == 0) {
        float r = (lane < 8) ? red[lane] : -1e30f;
#pragma unroll
        for (int o = 4; o; o >>= 1) r = fmaxf(r, __shfl_down_sync(0xffffffffu, r, o));
        if (lane == 0) red[0] = r;
    }
    __syncthreads();
    return red[0];
}

#define FF8(i, aval) do { u64 ad_ = dup2(aval); \
    acc[i][0] = ffma2(ad_, b01.x, acc[i][0]); \
    acc[i][1] = ffma2(ad_, b01.y, acc[i][1]); \
    acc[i][2] = ffma2(ad_, b23.x, acc[i][2]); \
    acc[i][3] = ffma2(ad_, b23.y, acc[i][3]); } while (0)

// ---- resident compute: nkk K-steps from smem As[nkk][68], Bs[nkk][132] ----
__device__ __forceinline__ void gemm_res(const float* __restrict__ As,
                                         const float* __restrict__ Bs,
                                         int nkk, float* __restrict__ Cp,
                                         int ldc, int n0)
{
    const int tid = threadIdx.x;
    if (tid >= 128) return;
    const int ty = tid >> 4, tx = tid & 15;
    u64 acc[8][4];
#pragma unroll
    for (int i = 0; i < 8; i++)
#pragma unroll
        for (int j = 0; j < 4; j++) acc[i][j] = 0ull;
    for (int k0 = 0; k0 < nkk; k0 += 8) {
#pragma unroll
        for (int k2 = 0; k2 < 8; k2++) {
            int kk = k0 + k2;
            float4 a0 = *(const float4*)(As + kk*68 + ty*4);
            float4 a1 = *(const float4*)(As + kk*68 + 32 + ty*4);
            ulonglong2 b01 = *(const ulonglong2*)(Bs + kk*132 + tx*4);
            ulonglong2 b23 = *(const ulonglong2*)(Bs + kk*132 + 64 + tx*4);
            FF8(0, a0.x); FF8(1, a0.y); FF8(2, a0.z); FF8(3, a0.w);
            FF8(4, a1.x); FF8(5, a1.y); FF8(6, a1.z); FF8(7, a1.w);
        }
    }
#pragma unroll
    for (int i = 0; i < 8; i++) {
        int r = (i < 4) ? (ty*4 + i) : (32 + ty*4 + (i - 4));
        float* cr = Cp + (size_t)r * ldc + n0;
        *(float4*)(cr + tx*4)      = f4of(acc[i][0], acc[i][1]);
        *(float4*)(cr + 64 + tx*4) = f4of(acc[i][2], acc[i][3]);
    }
}

// ---- big GEMM (f32x2, 128x128 tile): C = A @ B^T + bias ----
__device__ __forceinline__ void sgemm_f2_body(const float* __restrict__ A,
                                              const float* __restrict__ B,
                                              const float* __restrict__ bias,
                                              float* __restrict__ C, int N, int K)
{
    __shared__ __align__(16) float As[2112];
    __shared__ __align__(16) float Bs[2112];
    const int tid = threadIdx.x, ty = tid >> 4, tx = tid & 15;
    const int m0 = blockIdx.y << 7, n0 = blockIdx.x << 7;
    const int lm = tid & 127, lkq = tid >> 7;
    u64 acc[8][4];
#pragma unroll
    for (int i = 0; i < 8; i++)
#pragma unroll
        for (int j = 0; j < 4; j++) acc[i][j] = 0ull;
    const float* Ap = A + (size_t)(m0 + lm) * K + lkq * 4;
    const float* Bp = B + (size_t)(n0 + lm) * K + lkq * 4;
    const int nst = K >> 3;
    float4 va = *(const float4*)Ap, vb = *(const float4*)Bp;
    As[(lkq*4+0)*132+lm]=va.x; As[(lkq*4+1)*132+lm]=va.y;
    As[(lkq*4+2)*132+lm]=va.z; As[(lkq*4+3)*132+lm]=va.w;
    Bs[(lkq*4+0)*132+lm]=vb.x; Bs[(lkq*4+1)*132+lm]=vb.y;
    Bs[(lkq*4+2)*132+lm]=vb.z; Bs[(lkq*4+3)*132+lm]=vb.w;
    __syncthreads();
    for (int st = 0; st < nst; st++) {
        if (st + 1 < nst) {
            va = *(const float4*)(Ap + (st+1)*8);
            vb = *(const float4*)(Bp + (st+1)*8);
        }
        const float* Asl = As + (st & 1) * 1056;
        const float* Bsl = Bs + (st & 1) * 1056;
#pragma unroll
        for (int kk = 0; kk < 8; kk++) {
            float4 a0 = *(const float4*)(Asl + kk*132 + ty*4);
            float4 a1 = *(const float4*)(Asl + kk*132 + 64 + ty*4);
            ulonglong2 b01 = *(const ulonglong2*)(Bsl + kk*132 + tx*4);
            ulonglong2 b23 = *(const ulonglong2*)(Bsl + kk*132 + 64 + tx*4);
            FF8(0, a0.x); FF8(1, a0.y); FF8(2, a0.z); FF8(3, a0.w);
            FF8(4, a1.x); FF8(5, a1.y); FF8(6, a1.z); FF8(7, a1.w);
        }
        if (st + 1 < nst) {
            float* An = As + ((st+1) & 1) * 1056;
            float* Bn = Bs + ((st+1) & 1) * 1056;
            An[(lkq*4+0)*132+lm]=va.x; An[(lkq*4+1)*132+lm]=va.y;
            An[(lkq*4+2)*132+lm]=va.z; An[(lkq*4+3)*132+lm]=va.w;
            Bn[(lkq*4+0)*132+lm]=vb.x; Bn[(lkq*4+1)*132+lm]=vb.y;
            Bn[(lkq*4+2)*132+lm]=vb.z; Bn[(lkq*4+3)*132+lm]=vb.w;
            __syncthreads();
        }
    }
    const int c0 = n0 + tx*4, c1 = n0 + 64 + tx*4;
    float4 bi0 = *(const float4*)(bias + c0);
    float4 bi1 = *(const float4*)(bias + c1);
#pragma unroll
    for (int i = 0; i < 8; i++) {
        int r = m0 + ((i < 4) ? (ty*4 + i) : (64 + ty*4 + i - 4));
        float4 v0 = f4of(acc[i][0], acc[i][1]);
        float4 v1 = f4of(acc[i][2], acc[i][3]);
        v0.x += bi0.x; v0.y += bi0.y; v0.z += bi0.z; v0.w += bi0.w;
        v1.x += bi1.x; v1.y += bi1.y; v1.z += bi1.z; v1.w += bi1.w;
        *(float4*)(C + (size_t)r * N + c0) = v0;
        *(float4*)(C + (size_t)r * N + c1) = v1;
    }
}

__global__ __launch_bounds__(256, 2) void sgemm_gi_kernel(const float* __restrict__ W,
                                                          const float* __restrict__ bias) {
    sgemm_f2_body(g_xpe, W, bias, g_gi, G, D);
}
__global__ __launch_bounds__(256, 2) void sgemm_mem_kernel(const float* __restrict__ W,
                                                           const float* __restrict__ bias) {
    sgemm_f2_body(g_enc, W, bias, g_mem, D, D);
}

__global__ void pe_kernel(const float* __restrict__ dWih) {
    int idx = blockIdx.x * blockDim.x + threadIdx.x;
    if (idx < SEQ * D) {
        int k = idx % D, s = idx / D;
        const float c = 9.210340371976184f / (float)D;
        float dv  = expf(-(float)(k & ~1) * c);
        float arg = (float)s * dv;
        g_pe[idx] = (k & 1) ? cosf(arg) : sinf(arg);
    }
    if (idx < G) g_decW0[idx] = dWih[(size_t)idx * (D + 1)];
    if (idx < BS * D) g_h[idx] = 0.0f;
}

__global__ void prep_kernel(const float* __restrict__ x, const float* __restrict__ dWih) {
    size_t i4 = (size_t)blockIdx.x * blockDim.x + threadIdx.x;
    if (i4 < (size_t)MTOT * D / 4) {
        float4 v = ldcg4(x + i4 * 4);
        float4 p = *(const float4*)(g_pe + (i4 % (SEQ * D / 4)) * 4);
        add4(v, p);
        *(float4*)(g_xpe + i4 * 4) = v;
    }
    if (i4 < (size_t)G * D / 4) {
        int g = (int)(i4 * 4 / D), k = (int)(i4 * 4 % D);
        const float* src = dWih + (size_t)g * (D + 1) + 1 + k;
        float4 v = make_float4(src[0], src[1], src[2], src[3]);
        *(float4*)(g_decWc + i4 * 4) = v;
    }
}

// ---- persistent encoder: resident Whh slice, team-parallel gate ----
__global__ __launch_bounds__(NT, 2) void encoder_kernel(const float* __restrict__ Whh,
                                                        const float* __restrict__ bhh)
{
    __shared__ __align__(16) float Bs[48*132];
    __shared__ __align__(16) float As[48*68];
    const int bx = blockIdx.x, tid = threadIdx.x;
    const int nt = bx >> 4, kz = bx & 15;
    const int n0 = nt << 7, kbeg = kz * 48;
    float* Cp = g_part + (size_t)kz * BS * G;
    {
        int bn = tid & 127, kq0 = tid >> 7;
#pragma unroll
        for (int i = 0; i < 6; i++) {
            int kq = kq0 + 2 * i;
            float4 v = ldcg4(Whh + (size_t)(n0 + bn) * D + kbeg + (kq << 2));
            Bs[(kq*4+0)*132+bn]=v.x; Bs[(kq*4+1)*132+bn]=v.y;
            Bs[(kq*4+2)*132+bn]=v.z; Bs[(kq*4+3)*132+bn]=v.w;
        }
    }
    const int am = tid & 63, kq0 = tid >> 6;
    // gate teams: 4 threads per item, 64 teams/block
    const int q = tid & 3, team = tid >> 2;
    const int chunk = (bx < 192) ? 43 : 42;
    const int start = bx * 42 + ((bx < 192) ? bx : 192);
    const int gitem = (team < chunk) ? (start + team) : -1;
    const int gb = (gitem >= 0) ? (gitem / DQ) : 0;
    const int gj = (gitem >= 0) ? ((gitem - gb * DQ) << 2) : 0;
    grid_barrier();

    for (int s = 0; s < SEQ; s++) {
#pragma unroll
        for (int i = 0; i < 3; i++) {
            int kq = kq0 + 4 * i;
            float4 v = ldcg4(g_h + (size_t)am * D + kbeg + (kq << 2));
            As[(kq*4+0)*68+am]=v.x; As[(kq*4+1)*68+am]=v.y;
            As[(kq*4+2)*68+am]=v.z; As[(kq*4+3)*68+am]=v.w;
        }
        __syncthreads();
        gemm_res(As, Bs, 48, Cp, G, n0);
        grid_barrier();
        // team-parallel gate: lane q sums z = q, q+4, q+8, q+12
        {
            float4 t0 = make_float4(0.f,0.f,0.f,0.f), t1 = t0, t2 = t0;
            if (gitem >= 0) {
#pragma unroll
                for (int zz = 0; zz < 4; zz++) {
                    int z = q + 4 * zz;
                    const float* P = g_part + (size_t)(z * BS + gb) * G + gj;
                    add4(t0, ldcg4(P)); add4(t1, ldcg4(P + D)); add4(t2, ldcg4(P + 2*D));
                }
            }
#pragma unroll
            for (int o = 1; o <= 2; o <<= 1) {
                t0.x += __shfl_xor_sync(0xffffffffu, t0.x, o);
                t0.y += __shfl_xor_sync(0xffffffffu, t0.y, o);
                t0.z += __shfl_xor_sync(0xffffffffu, t0.z, o);
                t0.w += __shfl_xor_sync(0xffffffffu, t0.w, o);
                t1.x += __shfl_xor_sync(0xffffffffu, t1.x, o);
                t1.y += __shfl_xor_sync(0xffffffffu, t1.y, o);
                t1.z += __shfl_xor_sync(0xffffffffu, t1.z, o);
                t1.w += __shfl_xor_sync(0xffffffffu, t1.w, o);
                t2.x += __shfl_xor_sync(0xffffffffu, t2.x, o);
                t2.y += __shfl_xor_sync(0xffffffffu, t2.y, o);
                t2.z += __shfl_xor_sync(0xffffffffu, t2.z, o);
                t2.w += __shfl_xor_sync(0xffffffffu, t2.w, o);
            }
            if (gitem >= 0 && q == 0) {
                const float* gip = g_gi + ((size_t)gb * SEQ + s) * G + gj;
                float4 gr = ldcg4(gip), gz = ldcg4(gip + D), gn = ldcg4(gip + 2*D);
                float4 br = *(const float4*)(bhh + gj);
                float4 bz = *(const float4*)(bhh + D + gj);
                float4 bn = *(const float4*)(bhh + 2*D + gj);
                float4 hp = ldcg4(g_h + gb * D + gj);
                float4 hn;
                float r, zt, n;
                r = sigx(gr.x + br.x + t0.x); zt = sigx(gz.x + bz.x + t1.x);
                n = tanhx(gn.x + r * (bn.x + t2.x)); hn.x = (1.f - zt) * n + zt * hp.x;
                r = sigx(gr.y + br.y + t0.y); zt = sigx(gz.y + bz.y + t1.y);
                n = tanhx(gn.y + r * (bn.y + t2.y)); hn.y = (1.f - zt) * n + zt * hp.y;
                r = sigx(gr.z + br.z + t0.z); zt = sigx(gz.z + bz.z + t1.z);
                n = tanhx(gn.z + r * (bn.z + t2.z)); hn.z = (1.f - zt) * n + zt * hp.z;
                r = sigx(gr.w + br.w + t0.w); zt = sigx(gz.w + bz.w + t1.w);
                n = tanhx(gn.w + r * (bn.w + t2.w)); hn.w = (1.f - zt) * n + zt * hp.w;
                *(float4*)(g_h + gb * D + gj) = hn;
                *(float4*)(g_enc + ((size_t)gb * SEQ + s) * D + gj) = hn;
            }
        }
        grid_barrier();
    }
}

// ---- persistent decoder: dynamic smem, resident B for P1 AND P3 ----
__global__ __launch_bounds__(NT, 2) void decoder_kernel(
    const float* __restrict__ qW,  const float* __restrict__ qb,
    const float* __restrict__ pW,  const float* __restrict__ pb,
    const float* __restrict__ dWih, const float* __restrict__ dWhh,
    const float* __restrict__ bih, const float* __restrict__ bhh,
    const float* __restrict__ tW,  const float* __restrict__ tb,
    float* __restrict__ out)
{
    extern __shared__ __align__(16) float dynsm[];
    float* Bs1 = dynsm;
    float* Bs3 = dynsm + 64*132;
    float* As  = dynsm + 64*132 + 48*132;
    __shared__ __align__(16) float s_q[D];
    __shared__ __align__(16) float s_pw[D];
    __shared__ float s_w[80];
    __shared__ float red[8];
    const int bx = blockIdx.x, tid = threadIdx.x;
    const int nt1 = bx / 12, kz1 = bx % 12;
    const int kbeg1 = kz1 * 64;
    const float* B1src; float* Cp1; int n01, ldc1;
    if (nt1 < 6) { B1src = qW;   n01 = nt1 << 7;       Cp1 = g_qpart + (size_t)kz1 * BS * D; ldc1 = D; }
    else         { B1src = dWhh; n01 = (nt1 - 6) << 7; Cp1 = g_part2 + (size_t)kz1 * BS * G; ldc1 = G; }
    const int nt3 = bx >> 4, kz3 = bx & 15;
    const int n03 = nt3 << 7, kbeg3 = kz3 * 48;
    {
        int bn = tid & 127, kq0 = tid >> 7;
#pragma unroll
        for (int i = 0; i < 8; i++) {
            int kq = kq0 + 2 * i;
            float4 v = ldcg4(B1src + (size_t)(n01 + bn) * D + kbeg1 + (kq << 2));
            Bs1[(kq*4+0)*132+bn]=v.x; Bs1[(kq*4+1)*132+bn]=v.y;
            Bs1[(kq*4+2)*132+bn]=v.z; Bs1[(kq*4+3)*132+bn]=v.w;
        }
#pragma unroll
        for (int i = 0; i < 6; i++) {
            int kq = kq0 + 2 * i;
            float4 v = ldcg4(g_decWc + (size_t)(n03 + bn) * D + kbeg3 + (kq << 2));
            Bs3[(kq*4+0)*132+bn]=v.x; Bs3[(kq*4+1)*132+bn]=v.y;
            Bs3[(kq*4+2)*132+bn]=v.z; Bs3[(kq*4+3)*132+bn]=v.w;
        }
    }
    {
        int idx = bx * NT + tid;
        if (idx < BS * D) g_h[idx] = 0.0f;
    }
    grid_barrier();

    for (int t = 0; t < TSTEPS; t++) {
        // P1: fill A (h slice 64x64), resident 64-kk GEMM
        {
            int am = tid & 63, kq0 = tid >> 6;
#pragma unroll
            for (int i = 0; i < 4; i++) {
                int kq = kq0 + 4 * i;
                float4 v = ldcg4(g_h + (size_t)am * D + kbeg1 + (kq << 2));
                As[(kq*4+0)*68+am]=v.x; As[(kq*4+1)*68+am]=v.y;
                As[(kq*4+2)*68+am]=v.z; As[(kq*4+3)*68+am]=v.w;
            }
            __syncthreads();
            gemm_res(As, Bs1, 64, Cp1, ldc1, n01);
        }
        grid_barrier();
        // P2: logits + local softmax + unnormalized quarter-context (256 blocks)
        if (bx < 256) {
            int b = bx >> 2, qtr = bx & 3;
            int sb = qtr * 75;
            if (tid < DQ) {
                int j = tid << 2;
                float4 v = *(const float4*)(qb + j);
#pragma unroll
                for (int z = 0; z < 12; z++)
                    add4(v, ldcg4(g_qpart + (size_t)(z * BS + b) * D + j));
                *(float4*)&s_q[j]  = v;
                *(float4*)&s_pw[j] = *(const float4*)(pW + j);
            }
            __syncthreads();
            const u64 tC0 = dup2(-2.76076847742355e-16f), tC1 = dup2(2.00018790482477e-13f);
            const u64 tC2 = dup2(-8.60467152213735e-11f), tC3 = dup2(5.12229709037114e-08f);
            const u64 tC4 = dup2(1.48572235717979e-05f),  tC5 = dup2(6.37261928875436e-04f);
            const u64 tC6 = dup2(4.89352455891786e-03f);
            const u64 tQ0 = dup2(1.19825839466702e-06f),  tQ1 = dup2(1.18534705686654e-04f);
            const u64 tQ2 = dup2(2.26843463243900e-03f),  tQ3 = dup2(4.89352518554385e-03f);
            const u64 tTWO = dup2(2.0f);
            int w = tid >> 5, lane = tid & 31;
            for (int s = w; s < 75; s += 8) {
                const float* mrow = g_mem + ((size_t)b * SEQ + sb + s) * D;
                u64 acc2 = 0ull;
#pragma unroll
                for (int it = 0; it < 6; it++) {
                    int k = (lane << 2) + it * 128;
                    float4 m4 = ldcg4(mrow + k);
                    float4 q4 = *(const float4*)&s_q[k];
                    u64 xa = pack2(clampt(m4.x + q4.x), clampt(m4.y + q4.y));
                    u64 xb = pack2(clampt(m4.z + q4.z), clampt(m4.w + q4.w));
                    u64 ta, tb2;
                    TANH2(ta, xa);
                    TANH2(tb2, xb);
                    ulonglong2 w2 = *(const ulonglong2*)&s_pw[k];
                    acc2 = ffma2(w2.x, ta, acc2);
                    acc2 = ffma2(w2.y, tb2, acc2);
                }
                float2 af = unp2(acc2);
                float acc = af.x + af.y;
#pragma unroll
                for (int o = 16; o; o >>= 1) acc += __shfl_down_sync(0xffffffffu, acc, o);
                if (lane == 0) s_w[s] = acc;
            }
            float lv = (tid < 75) ? s_w[tid] : -1e30f;
            float m = redMax(lv, red);
            float ev = (tid < 75) ? __expf(s_w[tid] - m) : 0.0f;
            float S = redSum(ev, red);
            if (tid < 75) s_w[tid] = ev;
            if (tid == 0) g_stat[qtr * BS + b] = make_float2(m, S);
            __syncthreads();
            if (tid < DQ) {
                float4 c4 = make_float4(0.f, 0.f, 0.f, 0.f);
                const float* ep = g_enc + ((size_t)b * SEQ + sb) * D + (tid << 2);
#pragma unroll 5
                for (int s = 0; s < 75; s++) {
                    float wv = s_w[s];
                    float4 e4 = ldcg4(ep + (size_t)s * D);
                    c4.x += wv * e4.x; c4.y += wv * e4.y;
                    c4.z += wv * e4.z; c4.w += wv * e4.w;
                }
                *(float4*)&g_ctxp[qtr][b * D + (tid << 2)] = c4;
            }
        }
        grid_barrier();
        // P3: fill A = softmax-combined ctx (64x48), resident 48-kk GEMM
        {
            int am = tid & 63, kq0 = tid >> 6;
            float2 s0 = g_stat[am], s1 = g_stat[BS + am];
            float2 s2 = g_stat[2*BS + am], s3 = g_stat[3*BS + am];
            float M = fmaxf(fmaxf(s0.x, s1.x), fmaxf(s2.x, s3.x));
            float e0 = __expf(s0.x - M), e1 = __expf(s1.x - M);
            float e2 = __expf(s2.x - M), e3 = __expf(s3.x - M);
            float den = __fdividef(1.0f, s0.y*e0 + s1.y*e1 + s2.y*e2 + s3.y*e3);
            float al0 = e0*den, al1 = e1*den, al2 = e2*den, al3 = e3*den;
            const float* Ab = g_ctxp[0] + (size_t)am * D + kbeg3;
#pragma unroll
            for (int i = 0; i < 3; i++) {
                int kq = kq0 + 4 * i;
                float4 q0 = ldcg4(Ab + (kq << 2));
                float4 q1 = ldcg4(Ab + BS*D + (kq << 2));
                float4 q2 = ldcg4(Ab + 2*BS*D + (kq << 2));
                float4 q3 = ldcg4(Ab + 3*BS*D + (kq << 2));
                float4 v;
                v.x = al0*q0.x + al1*q1.x + al2*q2.x + al3*q3.x;
                v.y = al0*q0.y + al1*q1.y + al2*q2.y + al3*q3.y;
                v.z = al0*q0.z + al1*q1.z + al2*q2.z + al3*q3.z;
                v.w = al0*q0.w + al1*q1.w + al2*q2.w + al3*q3.w;
                As[(kq*4+0)*68+am]=v.x; As[(kq*4+1)*68+am]=v.y;
                As[(kq*4+2)*68+am]=v.z; As[(kq*4+3)*68+am]=v.w;
            }
            __syncthreads();
            gemm_res(As, Bs3, 48, g_part + (size_t)kz3 * BS * G, G, n03);
        }
        grid_barrier();
        // P4: gate + prediction (64 blocks)
        if (bx < 64) {
            int b = bx;
            float last = (t == 0) ? 0.0f : __ldcg(&out[b * TSTEPS + t - 1]);
            float psum = 0.0f;
            if (tid < DQ) {
                int j = tid << 2;
                float4 s0 = make_float4(0.f,0.f,0.f,0.f), s1 = s0, s2 = s0;
                float4 u0 = s0, u1 = s0, u2 = s0;
#pragma unroll
                for (int z = 0; z < 16; z++) {
                    const float* P = g_part + (size_t)(z * BS + b) * G + j;
                    add4(s0, ldcg4(P)); add4(s1, ldcg4(P + D)); add4(s2, ldcg4(P + 2*D));
                }
#pragma unroll
                for (int z = 0; z < 12; z++) {
                    const float* Q = g_part2 + (size_t)(z * BS + b) * G + j;
                    add4(u0, ldcg4(Q)); add4(u1, ldcg4(Q + D)); add4(u2, ldcg4(Q + 2*D));
                }
                float4 w0 = *(const float4*)(g_decW0 + j);
                float4 w1 = *(const float4*)(g_decW0 + D + j);
                float4 w2 = *(const float4*)(g_decW0 + 2*D + j);
                float4 b0 = *(const float4*)(bih + j);
                float4 b1 = *(const float4*)(bih + D + j);
                float4 b2 = *(const float4*)(bih + 2*D + j);
                float4 c0 = *(const float4*)(bhh + j);
                float4 c1 = *(const float4*)(bhh + D + j);
                float4 c2 = *(const float4*)(bhh + 2*D + j);
                float4 hp = ldcg4(g_h + b * D + j);
                float4 tw = *(const float4*)(tW + j);
                float4 hn;
                float r, zt, n;
                r  = sigx(b0.x + last * w0.x + s0.x + c0.x + u0.x);
                zt = sigx(b1.x + last * w1.x + s1.x + c1.x + u1.x);
                n  = tanhx(b2.x + last * w2.x + s2.x + r * (c2.x + u2.x));
                hn.x = (1.f - zt) * n + zt * hp.x;
                r  = sigx(b0.y + last * w0.y + s0.y + c0.y + u0.y);
                zt = sigx(b1.y + last * w1.y + s1.y + c1.y + u1.y);
                n  = tanhx(b2.y + last * w2.y + s2.y + r * (c2.y + u2.y));
                hn.y = (1.f - zt) * n + zt * hp.y;
                r  = sigx(b0.z + last * w0.z + s0.z + c0.z + u0.z);
                zt = sigx(b1.z + last * w1.z + s1.z + c1.z + u1.z);
                n  = tanhx(b2.z + last * w2.z + s2.z + r * (c2.z + u2.z));
                hn.z = (1.f - zt) * n + zt * hp.z;
                r  = sigx(b0.w + last * w0.w + s0.w + c0.w + u0.w);
                zt = sigx(b1.w + last * w1.w + s1.w + c1.w + u1.w);
                n  = tanhx(b2.w + last * w2.w + s2.w + r * (c2.w + u2.w));
                hn.w = (1.f - zt) * n + zt * hp.w;
                *(float4*)(g_h + b * D + j) = hn;
                psum = tw.x * hn.x + tw.y * hn.y + tw.z * hn.z + tw.w * hn.w;
            }
            float tot = redSum(psum, red);
            if (tid == 0) out[b * TSTEPS + t] = tot + tb[0];
        }
        grid_barrier();
    }
}

#define DEC_DYNSM ((64*132 + 48*132 + 64*68) * (int)sizeof(float))

extern "C" void kernel_launch(void* const* d_in, const int* in_sizes, int n_in,
                              void* d_out, int out_size) {
    const float* x       = (const float*)d_in[0];
    const float* enc_Wih = (const float*)d_in[1];
    const float* enc_Whh = (const float*)d_in[2];
    const float* enc_bih = (const float*)d_in[3];
    const float* enc_bhh = (const float*)d_in[4];
    const float* dec_Wih = (const float*)d_in[5];
    const float* dec_Whh = (const float*)d_in[6];
    const float* dec_bih = (const float*)d_in[7];
    const float* dec_bhh = (const float*)d_in[8];
    const float* qW      = (const float*)d_in[9];
    const float* qb      = (const float*)d_in[10];
    const float* mW      = (const float*)d_in[11];
    const float* mb      = (const float*)d_in[12];
    const float* pW      = (const float*)d_in[13];
    const float* pb      = (const float*)d_in[14];
    const float* tW      = (const float*)d_in[15];
    const float* tb      = (const float*)d_in[16];
    float* out = (float*)d_out;

    static int smem_set = 0;
    if (!smem_set) {
        cudaFuncSetAttribute(decoder_kernel,
                             cudaFuncAttributeMaxDynamicSharedMemorySize, DEC_DYNSM);
        smem_set = 1;
    }

    pe_kernel<<<(SEQ * D + 255) / 256, 256>>>(dec_Wih);
    prep_kernel<<<(MTOT * D / 4 + 255) / 256, 256>>>(x, dec_Wih);
    sgemm_gi_kernel<<<dim3(G / 128, MTOT / 128), 256>>>(enc_Wih, enc_bih);
    encoder_kernel<<<NB, NT>>>(enc_Whh, enc_bhh);
    sgemm_mem_kernel<<<dim3(D / 128, MTOT / 128), 256>>>(mW, mb);
    decoder_kernel<<<NB, NT, DEC_DYNSM>>>(qW, qb, pW, pb, dec_Wih, dec_Whh,
                                          dec_bih, dec_bhh, tW, tb, out);
}